// round 5
// baseline (speedup 1.0000x reference)
#include <cuda_runtime.h>
#include <math.h>

// DDPLL — sequential decision-directed PLL, fused unwrap + output rotation.
//
// The unwrap(period=pi/2) gate makes the output discretely sensitive to ulp-level
// trajectory error vs the JAX f32 reference (one flipped gate = pi/2 tail rotation
// = rel_err 7.8e-2, observed). All gate activity is in the pilot region, so there
// we replicate XLA:GPU's compiled forward+backward chain value-for-value:
//   z = y * exp(i*phi)            (libdevice sinf/cosf; exp(0)=1 exact)
//   diff = z - x
//   a = hypot_xla(diff)           (max/min scaled: mx*sqrt(1 + (mn/mx)^2), sqrt.rn)
//   t = 2a (exact); w = conj(diff)/a  (Smith complex-div by real: dr/a, -di/a)
//   zbar = t*w;  ebar = zbar*y;  g = -(ebar_r*sin + ebar_i*cos)   [= 2*Im(z conj x)]
// with natural expression trees so nvcc's FMA contraction mirrors XLA's LLVM
// contraction. The momentum filter collapses exactly (u[0]==u[2] bitwise from zero
// init => u0_k == g_k under any contraction), so carried state is just phi.
//
// DD region (k>=LEAD): per-axis QAM-16 slicer + closed-form g. Its ulp noise cannot
// trip the pi/4 gate (would need |g|>7.9, a >6-sigma event) and only perturbs theta
// by ~1e-6.
//
// unwrap fused on the fly with numpy semantics (floored mod, |dd|>=pi/4 gate,
// boundary-ambiguity fix); outputs rotated with direct sinf/cosf(theta+C) off-chain.

#define NSYMB   40000
#define NMODES  256
#define LEAD    20000
#define DPF     8

__global__ __launch_bounds__(32, 1)
void ddpll_kernel(const float* __restrict__ Er,
                  const float* __restrict__ Eim,
                  const float* __restrict__ Txr,
                  const float* __restrict__ Txi,
                  const float* __restrict__ eta,
                  float*       __restrict__ out)
{
    const int m = blockIdx.x * 32 + threadIdx.x;   // mode 0..255

    const float Kv = tanhf(eta[0]);

    float2* __restrict__ eo_out    = reinterpret_cast<float2*>(out);
    float*  __restrict__ theta_out = out + (size_t)NSYMB * NMODES * 2;

    const float PERIOD   = 1.5707963705062866f;   // (float)(pi/2)
    const float INTERVAL = 0.5f * PERIOD;         // == (float)(pi/4)

    // QAM-16 slicer constants (unit-energy grid)
    const float QB = 0.6324555320336759f;   // 2/sqrt(10)
    const float L1 = 0.31622776601683794f;  // 1/sqrt(10)
    const float L3 = 0.9486832980505138f;   // 3/sqrt(10)

    float phi = 0.0f;
    float prev_theta = 0.0f;
    float C = 0.0f;

    // input prefetch ring (keeps loads off the phi chain)
    float fyr[DPF], fyi[DPF], fxr[DPF], fxi[DPF];
#pragma unroll
    for (int j = 0; j < DPF; ++j) {
        const int idx = j * NMODES + m;
        fyr[j] = Er[idx];  fyi[j] = Eim[idx];
        fxr[j] = Txr[idx]; fxi[j] = Txi[idx];
    }

    for (int k0 = 0; k0 < NSYMB; k0 += DPF) {
#pragma unroll
        for (int j = 0; j < DPF; ++j) {
            const int k = k0 + j;
            const float yr = fyr[j], yi = fyi[j];
            const float xr = fxr[j], xi = fxi[j];

            if (k + DPF < NSYMB) {
                const int idx = (k + DPF) * NMODES + m;
                fyr[j] = Er[idx];  fyi[j] = Eim[idx];
                fxr[j] = Txr[idx]; fxi[j] = Txi[idx];
            }

            // e = exp(i*phi) — XLA complex Exp: exp(0)*cos, exp(0)*sin, libdevice
            const float s = sinf(phi);
            const float c = cosf(phi);
            // z = mul(y, e): re = yr*c - yi*s ; im = yr*s + yi*c  (XLA emission order)
            const float zr = yr * c - yi * s;
            const float zi = yr * s + yi * c;

            float g;
            if (k < LEAD) {
                // ---- pilot: replicate XLA autodiff chain ----
                const float dr = zr - xr;
                const float di = zi - xi;
                // a = EmitHypot(dr, di)
                const float aa = fabsf(dr), ab = fabsf(di);
                const float mx = fmaxf(aa, ab);
                const float mn = fminf(aa, ab);
                if (mx != 0.0f) {
                    const float r  = mn / mx;
                    const float a  = mx * sqrtf(1.0f + r * r);
                    // abs-VJP residual w = conj(diff)/a (Smith div by real)
                    const float t  = a + a;          // 2a exact (pil weight = 1)
                    const float qr = dr / a;
                    const float qi = (-di) / a;
                    // zbar' = mul(complex(t,0), w): zero terms exact
                    const float dbr = t * qr;
                    const float dbi = t * qi;
                    // ebar' = mul(zbar', y)
                    const float ebr = dbr * yr - dbi * yi;
                    const float ebi = dbr * yi + dbi * yr;
                    // vbar' = mul(ebar', e);  phibar = imag(neg(vbar'))
                    g = -(ebr * s + ebi * c);
                } else {
                    g = 0.0f;                        // diff == 0 (measure zero)
                }
            } else {
                // ---- decision-directed: per-axis slicer + closed-form grad ----
                const float cr = copysignf((fabsf(zr) < QB) ? L1 : L3, zr);
                const float ci = copysignf((fabsf(zi) < QB) ? L1 : L3, zi);
                g = 2.0f * (zi * cr - zr * ci);
            }

            // ---- unwrap (numpy semantics), off the phi chain ----
            const float theta_raw = phi;
            const float dd = theta_raw - prev_theta;
            if (fabsf(dd) >= INTERVAL) {
                float t2 = dd + INTERVAL;
                float r2 = fmodf(t2, PERIOD);
                if (r2 < 0.0f) r2 += PERIOD;         // floored mod
                float ddmod = r2 - INTERVAL;
                if (ddmod == -INTERVAL && dd > 0.0f) ddmod = INTERVAL;
                C += (ddmod - dd);
            }
            prev_theta = theta_raw;
            const float theta_u = theta_raw + C;

            // ---- output rotation: Eo = Ei * exp(i*theta_u) ----
            const float su = sinf(theta_u);
            const float cu = cosf(theta_u);
            float2 eo;
            eo.x = yr * cu - yi * su;
            eo.y = yr * su + yi * cu;
            __stcs(&eo_out[k * NMODES + m], eo);
            __stcs(&theta_out[k * NMODES + m], theta_u);

            // ---- chain update (u0_k == g_k exactly) ----
            phi = phi - Kv * g;
        }
    }
}

extern "C" void kernel_launch(void* const* d_in, const int* in_sizes, int n_in,
                              void* d_out, int out_size)
{
    const float* Er  = (const float*)d_in[0];
    const float* Eim = (const float*)d_in[1];
    const float* Txr = (const float*)d_in[2];
    const float* Txi = (const float*)d_in[3];
    const float* eta = (const float*)d_in[4];
    float* out = (float*)d_out;

    ddpll_kernel<<<NMODES / 32, 32>>>(Er, Eim, Txr, Txi, eta, out);
}

// round 7
// speedup vs baseline: 1.5960x; 1.5960x over previous
#include <cuda_runtime.h>
#include <math.h>

// DDPLL — (1) sequential phase-tracking kernel (latency-bound, 1 thread/mode),
//          (2) massively parallel output-rotation kernel.
//
// Trajectory arithmetic (kernel 1) is gate-critical: unwrap(period=pi/2) decisions
// flip on ulp-level divergence from the JAX f32 reference (one flip = pi/2 tail
// rotation = ~6-8e-2 rel_err; seen in R3/R4/R6). Proven-safe config (R5 PASS):
//   - libdevice sincosf for the trajectory trig (BOTH regions; R6 showed DD-region
//     __sincosf flips a gate at k~20400 — g has an exponential tail via |y|).
//   - Pilot region: XLA autodiff chain value-for-value (EmitHypot abs, the
//     2a*(conj(d)/a) double-rounded VJP, XLA-order complex muls, natural FMA trees).
//   - DD region: per-axis QAM-16 slicer + closed-form g (= what autodiff-through-min
//     computes; its ulp noise never flipped a gate in R5).
// Momentum filter collapses exactly (u[0]==u[2] bitwise from zero init => u0_k==g_k).
//
// Kernel 2 rotates outputs with __sincosf: output-only (no feedback), abs err ~1e-5.

#define NSYMB   40000
#define NMODES  256
#define LEAD    20000
#define DPF     8

__global__ __launch_bounds__(32, 1)
void ddpll_phase_kernel(const float* __restrict__ Er,
                        const float* __restrict__ Eim,
                        const float* __restrict__ Txr,
                        const float* __restrict__ Txi,
                        const float* __restrict__ eta,
                        float*       __restrict__ out)
{
    const int m = blockIdx.x * 32 + threadIdx.x;   // mode 0..255

    const float Kv = tanhf(eta[0]);

    float* __restrict__ theta_out = out + (size_t)NSYMB * NMODES * 2;

    const float PERIOD   = 1.5707963705062866f;   // (float)(pi/2)
    const float INTERVAL = 0.5f * PERIOD;         // (float)(pi/4)

    // QAM-16 slicer constants (unit-energy grid)
    const float QB = 0.6324555320336759f;   // 2/sqrt(10)
    const float L1 = 0.31622776601683794f;  // 1/sqrt(10)
    const float L3 = 0.9486832980505138f;   // 3/sqrt(10)

    float phi = 0.0f;
    float prev_theta = 0.0f;
    float C = 0.0f;

    // prefetch ring: keeps loads off the phi chain
    float fyr[DPF], fyi[DPF], fxr[DPF], fxi[DPF];
#pragma unroll
    for (int j = 0; j < DPF; ++j) {
        const int idx = j * NMODES + m;
        fyr[j] = Er[idx];  fyi[j] = Eim[idx];
        fxr[j] = Txr[idx]; fxi[j] = Txi[idx];
    }

    for (int k0 = 0; k0 < NSYMB; k0 += DPF) {
#pragma unroll
        for (int j = 0; j < DPF; ++j) {
            const int k = k0 + j;
            const float yr = fyr[j], yi = fyi[j];
            const float xr = fxr[j], xi = fxi[j];

            if (k + DPF < NSYMB) {
                const int idx = (k + DPF) * NMODES + m;
                fyr[j] = Er[idx];  fyi[j] = Eim[idx];
                if (k + DPF < LEAD) {                 // x only used in pilot region
                    fxr[j] = Txr[idx]; fxi[j] = Txi[idx];
                }
            }

            // trajectory trig: libdevice (bit-matches reference; R5-proven)
            float s, c;
            sincosf(phi, &s, &c);
            const float zr = yr * c - yi * s;
            const float zi = yr * s + yi * c;

            float g;
            if (k < LEAD) {
                // ---- pilot: exact XLA autodiff chain (do not touch) ----
                const float dr = zr - xr;
                const float di = zi - xi;
                const float aa = fabsf(dr), ab = fabsf(di);
                const float mx = fmaxf(aa, ab);
                const float mn = fminf(aa, ab);
                if (mx != 0.0f) {
                    const float r  = mn / mx;
                    const float a  = mx * sqrtf(1.0f + r * r);
                    const float t  = a + a;
                    const float qr = dr / a;
                    const float qi = (-di) / a;
                    const float dbr = t * qr;
                    const float dbi = t * qi;
                    const float ebr = dbr * yr - dbi * yi;
                    const float ebi = dbr * yi + dbi * yr;
                    g = -(ebr * s + ebi * c);
                } else {
                    g = 0.0f;
                }
            } else {
                // ---- DD: per-axis slicer + closed-form grad ----
                const float cr = copysignf((fabsf(zr) < QB) ? L1 : L3, zr);
                const float ci = copysignf((fabsf(zi) < QB) ? L1 : L3, zi);
                g = 2.0f * (zi * cr - zr * ci);
            }

            // ---- unwrap (numpy semantics), off the phi chain ----
            const float theta_raw = phi;
            const float dd = theta_raw - prev_theta;
            if (fabsf(dd) >= INTERVAL) {
                float t2 = dd + INTERVAL;
                float r2 = fmodf(t2, PERIOD);
                if (r2 < 0.0f) r2 += PERIOD;          // floored mod
                float ddmod = r2 - INTERVAL;
                if (ddmod == -INTERVAL && dd > 0.0f) ddmod = INTERVAL;
                C += (ddmod - dd);
            }
            prev_theta = theta_raw;
            __stcs(&theta_out[k * NMODES + m], theta_raw + C);

            // ---- chain update (u0_k == g_k exactly) ----
            phi = phi - Kv * g;
        }
    }
}

// Kernel 2: parallel output rotation, one thread per (k, m).
__global__ __launch_bounds__(256)
void ddpll_rotate_kernel(const float* __restrict__ Er,
                         const float* __restrict__ Eim,
                         float*       __restrict__ out)
{
    const int t = blockIdx.x * 256 + threadIdx.x;    // 0 .. NSYMB*NMODES-1
    const float* __restrict__ theta_in = out + (size_t)NSYMB * NMODES * 2;
    float2* __restrict__ eo_out = reinterpret_cast<float2*>(out);

    const float th = theta_in[t];
    const float yr = Er[t];
    const float yi = Eim[t];
    float s, c;
    __sincosf(th, &s, &c);
    float2 eo;
    eo.x = yr * c - yi * s;
    eo.y = yr * s + yi * c;
    __stcs(&eo_out[t], eo);
}

extern "C" void kernel_launch(void* const* d_in, const int* in_sizes, int n_in,
                              void* d_out, int out_size)
{
    const float* Er  = (const float*)d_in[0];
    const float* Eim = (const float*)d_in[1];
    const float* Txr = (const float*)d_in[2];
    const float* Txi = (const float*)d_in[3];
    const float* eta = (const float*)d_in[4];
    float* out = (float*)d_out;

    ddpll_phase_kernel<<<NMODES / 32, 32>>>(Er, Eim, Txr, Txi, eta, out);
    ddpll_rotate_kernel<<<(NSYMB * NMODES) / 256, 256>>>(Er, Eim, out);
}

// round 11
// speedup vs baseline: 2.2982x; 1.4400x over previous
#include <cuda_runtime.h>
#include <math.h>

// DDPLL — (1) sequential phase-tracking kernel (latency-bound, 1 thread/mode),
//          (2) massively parallel output-rotation kernel.
//
// HARD CONSTRAINT (R3-R8 calibration): phi wanders to |phi|~50-100 rad (random
// walk; tx is independent of Ei), so the reference trajectory's rounding floor is
// ulp(phi)~4e-6. The unwrap(pi/2) gate flips on any sustained deviation at/above
// ~1e-7 => the phi-chain fp op sequence must be BITWISE identical to the R5/R7
// proven chain (libdevice sincosf + XLA autodiff grad chain + slicer). R8 (1-ulp
// custom trig) flipped a gate; R6 (__sincosf) flipped a gate. Frozen.
//
// Control-flow-only optimizations (fp ops untouched vs R7 banked pass):
//  - loop split pilot/DD/epilogue (removes per-step region + prefetch-bound branches)
//  - branchless exact unwrap: inline exact remainder (trunc + fmaf + select fixup;
//    fp remainders are exactly representable, so the final fmaf reproduces fmodf
//    bit-for-bit), gate/boundary as selects, unconditional C += (gated ? corr : 0)
//  - mx!=0 branch -> safe-denominator selects (identical bits when mx != 0)

#define NSYMB   40000
#define NMODES  256
#define LEAD    20000
#define DPF     8

__global__ __launch_bounds__(32, 1)
void ddpll_phase_kernel(const float* __restrict__ Er,
                        const float* __restrict__ Eim,
                        const float* __restrict__ Txr,
                        const float* __restrict__ Txi,
                        const float* __restrict__ eta,
                        float*       __restrict__ out)
{
    const int m = blockIdx.x * 32 + threadIdx.x;   // mode 0..255

    const float Kv = tanhf(eta[0]);

    float* __restrict__ theta_out = out + (size_t)NSYMB * NMODES * 2;

    const float PERIOD   = 1.5707963705062866f;   // (float)(pi/2)
    const float INV_P    = 0.6366197466850281f;   // (float)(1/PERIOD)
    const float INTERVAL = 0.5f * PERIOD;         // (float)(pi/4), exact halving

    // QAM-16 slicer constants (unit-energy grid)
    const float QB = 0.6324555320336759f;   // 2/sqrt(10)
    const float L1 = 0.31622776601683794f;  // 1/sqrt(10)
    const float L3 = 0.9486832980505138f;   // 3/sqrt(10)

    float phi = 0.0f;
    float prev_theta = 0.0f;
    float C = 0.0f;

    // prefetch ring
    float fyr[DPF], fyi[DPF], fxr[DPF], fxi[DPF];
#pragma unroll
    for (int j = 0; j < DPF; ++j) {
        const int idx = j * NMODES + m;
        fyr[j] = Er[idx];  fyi[j] = Eim[idx];
        fxr[j] = Txr[idx]; fxi[j] = Txi[idx];
    }

    // Branchless unwrap step: updates C, stores theta. All selects, no calls.
    // Reproduces: dd=theta-prev; if(|dd|>=I){ r=fmodf(dd+I,P); if(r<0)r+=P;
    //   ddmod=r-I; if(ddmod==-I && dd>0) ddmod=I; C += ddmod-dd; }
#define UNWRAP_STORE(kk)                                                      \
    {                                                                         \
        const float theta_raw = phi;                                          \
        const float dd = theta_raw - prev_theta;                              \
        const float t2 = dd + INTERVAL;                                       \
        float nq = truncf(t2 * INV_P);                                        \
        float r0 = fmaf(-nq, PERIOD, t2);                                     \
        /* quotient fixup toward fmod semantics (sign of t2, |r|<P) */        \
        float adj;                                                            \
        if (t2 > 0.0f) { adj = (r0 < 0.0f) ? -1.0f : ((r0 >= PERIOD) ? 1.0f : 0.0f); } \
        else           { adj = (r0 > 0.0f) ?  1.0f : ((r0 <= -PERIOD) ? -1.0f : 0.0f); } \
        nq += adj;                                                            \
        float r2 = fmaf(-nq, PERIOD, t2);      /* == fmodf(t2,P) bit-exact */ \
        r2 = (r2 < 0.0f) ? (r2 + PERIOD) : r2; /* floored mod, same rounding */ \
        float ddmod = r2 - INTERVAL;                                          \
        ddmod = (ddmod == -INTERVAL && dd > 0.0f) ? INTERVAL : ddmod;         \
        const float corr = (fabsf(dd) >= INTERVAL) ? (ddmod - dd) : 0.0f;     \
        C += corr;                                                            \
        prev_theta = theta_raw;                                               \
        __stcs(&theta_out[(kk) * NMODES + m], theta_raw + C);                 \
    }

    // ---------------- pilot loop: k in [0, LEAD) ----------------
    for (int k0 = 0; k0 < LEAD; k0 += DPF) {
#pragma unroll
        for (int j = 0; j < DPF; ++j) {
            const int k = k0 + j;
            const float yr = fyr[j], yi = fyi[j];
            const float xr = fxr[j], xi = fxi[j];

            {   // unconditional prefetch (k+DPF <= LEAD+7 < NSYMB)
                const int idx = (k + DPF) * NMODES + m;
                fyr[j] = Er[idx];  fyi[j] = Eim[idx];
                fxr[j] = Txr[idx]; fxi[j] = Txi[idx];
            }

            float s, c;
            sincosf(phi, &s, &c);
            const float zr = yr * c - yi * s;
            const float zi = yr * s + yi * c;

            // exact XLA autodiff chain (fp ops identical to R7)
            const float dr = zr - xr;
            const float di = zi - xi;
            const float aa = fabsf(dr), ab = fabsf(di);
            const float mx = fmaxf(aa, ab);
            const float mn = fminf(aa, ab);
            const bool  z0 = (mx == 0.0f);
            const float den1 = z0 ? 1.0f : mx;
            const float r  = mn / den1;
            const float a  = mx * sqrtf(1.0f + r * r);
            const float den2 = z0 ? 1.0f : a;
            const float t  = a + a;
            const float qr = dr / den2;
            const float qi = (-di) / den2;
            const float dbr = t * qr;
            const float dbi = t * qi;
            const float ebr = dbr * yr - dbi * yi;
            const float ebi = dbr * yi + dbi * yr;
            const float g = -(ebr * s + ebi * c);

            UNWRAP_STORE(k)
            phi = phi - Kv * g;
        }
    }

    // ---------------- DD main loop: k in [LEAD, NSYMB-DPF) ----------------
    // ring already holds y for k = LEAD..LEAD+DPF-1 from pilot prefetches
    for (int k0 = LEAD; k0 < NSYMB - DPF; k0 += DPF) {
#pragma unroll
        for (int j = 0; j < DPF; ++j) {
            const int k = k0 + j;
            const float yr = fyr[j], yi = fyi[j];

            {   // unconditional prefetch (k+DPF <= NSYMB-1)
                const int idx = (k + DPF) * NMODES + m;
                fyr[j] = Er[idx];  fyi[j] = Eim[idx];
            }

            float s, c;
            sincosf(phi, &s, &c);
            const float zr = yr * c - yi * s;
            const float zi = yr * s + yi * c;

            const float cr = copysignf((fabsf(zr) < QB) ? L1 : L3, zr);
            const float ci = copysignf((fabsf(zi) < QB) ? L1 : L3, zi);
            const float g = 2.0f * (zi * cr - zr * ci);

            UNWRAP_STORE(k)
            phi = phi - Kv * g;
        }
    }

    // ---------------- DD epilogue: last DPF steps, no prefetch ----------------
#pragma unroll
    for (int j = 0; j < DPF; ++j) {
        const int k = (NSYMB - DPF) + j;
        const float yr = fyr[j], yi = fyi[j];

        float s, c;
        sincosf(phi, &s, &c);
        const float zr = yr * c - yi * s;
        const float zi = yr * s + yi * c;

        const float cr = copysignf((fabsf(zr) < QB) ? L1 : L3, zr);
        const float ci = copysignf((fabsf(zi) < QB) ? L1 : L3, zi);
        const float g = 2.0f * (zi * cr - zr * ci);

        UNWRAP_STORE(k)
        phi = phi - Kv * g;
    }
#undef UNWRAP_STORE
}

// Kernel 2: parallel output rotation, one thread per (k, m).
__global__ __launch_bounds__(256)
void ddpll_rotate_kernel(const float* __restrict__ Er,
                         const float* __restrict__ Eim,
                         float*       __restrict__ out)
{
    const int t = blockIdx.x * 256 + threadIdx.x;    // 0 .. NSYMB*NMODES-1
    const float* __restrict__ theta_in = out + (size_t)NSYMB * NMODES * 2;
    float2* __restrict__ eo_out = reinterpret_cast<float2*>(out);

    const float th = theta_in[t];
    const float yr = Er[t];
    const float yi = Eim[t];
    float s, c;
    __sincosf(th, &s, &c);
    float2 eo;
    eo.x = yr * c - yi * s;
    eo.y = yr * s + yi * c;
    __stcs(&eo_out[t], eo);
}

extern "C" void kernel_launch(void* const* d_in, const int* in_sizes, int n_in,
                              void* d_out, int out_size)
{
    const float* Er  = (const float*)d_in[0];
    const float* Eim = (const float*)d_in[1];
    const float* Txr = (const float*)d_in[2];
    const float* Txi = (const float*)d_in[3];
    const float* eta = (const float*)d_in[4];
    float* out = (float*)d_out;

    ddpll_phase_kernel<<<NMODES / 32, 32>>>(Er, Eim, Txr, Txi, eta, out);
    ddpll_rotate_kernel<<<(NSYMB * NMODES) / 256, 256>>>(Er, Eim, out);
}

// round 13
// speedup vs baseline: 2.4268x; 1.0560x over previous
#include <cuda_runtime.h>
#include <math.h>

// DDPLL — 4 kernels:
//  1. ddpll_phase_kernel   : serial phi recurrence only (latency-bound, 1 thr/mode);
//                            stores RAW phi[k][m] into the theta slot of out.
//  2. ddpll_unwrap_partials: per-chunk sums of unwrap corrections (parallel).
//  3. ddpll_unwrap_scan    : per-mode exclusive prefix over chunk partials.
//  4. ddpll_apply_kernel   : recompute corr + running C, theta_u = phi + C,
//                            store theta_u AND rotate Eo = Ei*exp(i*theta_u).
//
// HARD CONSTRAINT (R3-R8 calibration): the phi-chain fp op sequence is BITWISE
// FROZEN at the R5/R7/R11-proven chain (libdevice sincosf + XLA autodiff grad in
// pilot + QAM slicer in DD). R6/__sincosf and R8/1-ulp-trig each flipped an
// unwrap gate; R11 digit-string-verified the frozen chain (rel_err 7.636109e-05).
//
// Unwrap offload correctness: corr_k is a pointwise function of (phi_k, phi_{k-1})
// computed with the exact reference fp ops => gate decisions and corr values are
// bitwise identical. Only the cumsum C is re-grouped (chunked scan), perturbing
// theta_u by ~1e-5 abs, strictly output-side (never feeds the trajectory).
//
// Scratch: __device__ globals (sanctioned scratch mechanism; no allocation).
// Determinism: every scratch cell is rewritten each call before any read.

#define NSYMB   40000
#define NMODES  256
#define LEAD    20000
#define DPF     8
#define NCHUNK  250
#define CHS     160     // NCHUNK * CHS == NSYMB

__device__ float g_partials[NMODES * NCHUNK];   // per-chunk corr sums -> excl prefix
__device__ float g_boundary[NMODES * NCHUNK];   // phi[c*CHS - 1] per (mode, chunk)

__global__ __launch_bounds__(32, 1)
void ddpll_phase_kernel(const float* __restrict__ Er,
                        const float* __restrict__ Eim,
                        const float* __restrict__ Txr,
                        const float* __restrict__ Txi,
                        const float* __restrict__ eta,
                        float*       __restrict__ out)
{
    const int m = blockIdx.x * 32 + threadIdx.x;   // mode 0..255

    const float Kv = tanhf(eta[0]);

    float* __restrict__ phi_out = out + (size_t)NSYMB * NMODES * 2;  // theta slot

    // QAM-16 slicer constants (unit-energy grid)
    const float QB = 0.6324555320336759f;   // 2/sqrt(10)
    const float L1 = 0.31622776601683794f;  // 1/sqrt(10)
    const float L3 = 0.9486832980505138f;   // 3/sqrt(10)

    float phi = 0.0f;

    // prefetch ring
    float fyr[DPF], fyi[DPF], fxr[DPF], fxi[DPF];
#pragma unroll
    for (int j = 0; j < DPF; ++j) {
        const int idx = j * NMODES + m;
        fyr[j] = Er[idx];  fyi[j] = Eim[idx];
        fxr[j] = Txr[idx]; fxi[j] = Txi[idx];
    }

    // ---------------- pilot loop: k in [0, LEAD) ----------------
    for (int k0 = 0; k0 < LEAD; k0 += DPF) {
#pragma unroll
        for (int j = 0; j < DPF; ++j) {
            const int k = k0 + j;
            const float yr = fyr[j], yi = fyi[j];
            const float xr = fxr[j], xi = fxi[j];

            {   // unconditional prefetch (k+DPF <= LEAD+7 < NSYMB)
                const int idx = (k + DPF) * NMODES + m;
                fyr[j] = Er[idx];  fyi[j] = Eim[idx];
                fxr[j] = Txr[idx]; fxi[j] = Txi[idx];
            }

            float s, c;
            sincosf(phi, &s, &c);
            const float zr = yr * c - yi * s;
            const float zi = yr * s + yi * c;

            // exact XLA autodiff chain (fp ops identical to R7/R11 — frozen)
            const float dr = zr - xr;
            const float di = zi - xi;
            const float aa = fabsf(dr), ab = fabsf(di);
            const float mx = fmaxf(aa, ab);
            const float mn = fminf(aa, ab);
            const bool  z0 = (mx == 0.0f);
            const float den1 = z0 ? 1.0f : mx;
            const float r  = mn / den1;
            const float a  = mx * sqrtf(1.0f + r * r);
            const float den2 = z0 ? 1.0f : a;
            const float t  = a + a;
            const float qr = dr / den2;
            const float qi = (-di) / den2;
            const float dbr = t * qr;
            const float dbi = t * qi;
            const float ebr = dbr * yr - dbi * yi;
            const float ebi = dbr * yi + dbi * yr;
            const float g = -(ebr * s + ebi * c);

            __stcs(&phi_out[k * NMODES + m], phi);   // raw pre-update phase
            phi = phi - Kv * g;
        }
    }

    // ---------------- DD main loop: k in [LEAD, NSYMB-DPF) ----------------
    for (int k0 = LEAD; k0 < NSYMB - DPF; k0 += DPF) {
#pragma unroll
        for (int j = 0; j < DPF; ++j) {
            const int k = k0 + j;
            const float yr = fyr[j], yi = fyi[j];

            {   // unconditional prefetch
                const int idx = (k + DPF) * NMODES + m;
                fyr[j] = Er[idx];  fyi[j] = Eim[idx];
            }

            float s, c;
            sincosf(phi, &s, &c);
            const float zr = yr * c - yi * s;
            const float zi = yr * s + yi * c;

            const float cr = copysignf((fabsf(zr) < QB) ? L1 : L3, zr);
            const float ci = copysignf((fabsf(zi) < QB) ? L1 : L3, zi);
            const float g = 2.0f * (zi * cr - zr * ci);

            __stcs(&phi_out[k * NMODES + m], phi);
            phi = phi - Kv * g;
        }
    }

    // ---------------- DD epilogue ----------------
#pragma unroll
    for (int j = 0; j < DPF; ++j) {
        const int k = (NSYMB - DPF) + j;
        const float yr = fyr[j], yi = fyi[j];

        float s, c;
        sincosf(phi, &s, &c);
        const float zr = yr * c - yi * s;
        const float zi = yr * s + yi * c;

        const float cr = copysignf((fabsf(zr) < QB) ? L1 : L3, zr);
        const float ci = copysignf((fabsf(zi) < QB) ? L1 : L3, zi);
        const float g = 2.0f * (zi * cr - zr * ci);

        __stcs(&phi_out[k * NMODES + m], phi);
        phi = phi - Kv * g;
    }
}

// Pointwise unwrap correction — EXACT reference fp ops (fmodf = libdevice).
__device__ __forceinline__ float unwrap_corr(float prev, float cur)
{
    const float PERIOD   = 1.5707963705062866f;   // (float)(pi/2)
    const float INTERVAL = 0.5f * PERIOD;         // (float)(pi/4)
    const float dd = cur - prev;
    if (fabsf(dd) < INTERVAL) return 0.0f;
    float r2 = fmodf(dd + INTERVAL, PERIOD);
    if (r2 < 0.0f) r2 += PERIOD;                  // floored mod
    float ddmod = r2 - INTERVAL;
    if (ddmod == -INTERVAL && dd > 0.0f) ddmod = INTERVAL;
    return ddmod - dd;
}

// Kernel 2: per-(mode, chunk) correction sums + boundary stash.
__global__ __launch_bounds__(NMODES)
void ddpll_unwrap_partials(const float* __restrict__ out)
{
    const int c = blockIdx.x;             // chunk 0..NCHUNK-1
    const int m = threadIdx.x;            // mode
    const float* __restrict__ phi_in = out + (size_t)NSYMB * NMODES * 2;

    float prev = (c == 0) ? 0.0f : phi_in[(c * CHS - 1) * NMODES + m];
    g_boundary[m * NCHUNK + c] = prev;

    float sum = 0.0f;
    for (int i = 0; i < CHS; ++i) {
        const int k = c * CHS + i;
        const float cur = phi_in[k * NMODES + m];
        if (k > 0) sum += unwrap_corr(prev, cur);
        prev = cur;
    }
    g_partials[m * NCHUNK + c] = sum;
}

// Kernel 3: per-mode exclusive prefix over chunk partials.
__global__ __launch_bounds__(NMODES)
void ddpll_unwrap_scan()
{
    const int m = threadIdx.x;
    float run = 0.0f;
    for (int c = 0; c < NCHUNK; ++c) {
        const float v = g_partials[m * NCHUNK + c];
        g_partials[m * NCHUNK + c] = run;
        run += v;
    }
}

// Kernel 4: apply running C, store theta_u, rotate outputs.
__global__ __launch_bounds__(NMODES)
void ddpll_apply_kernel(const float* __restrict__ Er,
                        const float* __restrict__ Eim,
                        float*       __restrict__ out)
{
    const int c = blockIdx.x;
    const int m = threadIdx.x;
    float* __restrict__ theta_io = out + (size_t)NSYMB * NMODES * 2;  // phi in, theta out
    float2* __restrict__ eo_out  = reinterpret_cast<float2*>(out);

    float C    = g_partials[m * NCHUNK + c];
    float prev = g_boundary[m * NCHUNK + c];

    for (int i = 0; i < CHS; ++i) {
        const int k = c * CHS + i;
        const float cur = theta_io[k * NMODES + m];
        if (k > 0) C += unwrap_corr(prev, cur);
        prev = cur;

        const float th = cur + C;
        __stcs(&theta_io[k * NMODES + m], th);

        const float yr = Er[k * NMODES + m];
        const float yi = Eim[k * NMODES + m];
        float s, cc;
        __sincosf(th, &s, &cc);
        float2 eo;
        eo.x = yr * cc - yi * s;
        eo.y = yr * s + yi * cc;
        __stcs(&eo_out[k * NMODES + m], eo);
    }
}

extern "C" void kernel_launch(void* const* d_in, const int* in_sizes, int n_in,
                              void* d_out, int out_size)
{
    const float* Er  = (const float*)d_in[0];
    const float* Eim = (const float*)d_in[1];
    const float* Txr = (const float*)d_in[2];
    const float* Txi = (const float*)d_in[3];
    const float* eta = (const float*)d_in[4];
    float* out = (float*)d_out;

    ddpll_phase_kernel<<<NMODES / 32, 32>>>(Er, Eim, Txr, Txi, eta, out);
    ddpll_unwrap_partials<<<NCHUNK, NMODES>>>(out);
    ddpll_unwrap_scan<<<1, NMODES>>>();
    ddpll_apply_kernel<<<NCHUNK, NMODES>>>(Er, Eim, out);
}

// round 14
// speedup vs baseline: 3.1957x; 1.3168x over previous
#include <cuda_runtime.h>
#include <math.h>

// DDPLL — pilot serial + DD region chunk-parallel (bitwise via synchronize/stitch/fix):
//  K1 phase: blocks 0-7  = serial pilot [0,20000) + exact DD stub [20000,20480)
//            blocks 8-71 = speculative DD chunks (seed 0, warm 480 + body 2440),
//            running CONCURRENTLY on other SMs (hidden under the 5.5ms pilot).
//  K2 stitch: resolve pi/2 branch integers n_c by chaining boundary comparisons.
//  K3 fix: per chunk, de-rotate spec seed by n_c*pi/2, warm 128 steps (bitwise
//          collapse onto the reference fp orbit), then write body phi bitwise.
//  K4/K5/K6: unwrap partials / scan / apply+rotate (as R13, finer chunks).
//
// FROZEN (R3-R13 calibration): the phi-step fp op sequence (libdevice sincosf,
// XLA autodiff grad in pilot, QAM slicer in DD) — bitwise identical everywhere.
// DD synchronization: f'(phi) = 1 - 2*Kv*<z,slicer(z)>, <z,c> >= 0 on every
// Voronoi cell => |f'| <= 1, E[ln|f'|] ~ -0.22/step => spec converges to
// ref + n*pi/2 within <1 ulp; fix sweep re-seeded within ~2 ulp of the exact fp
// orbit collapses bitwise (P(fail) ~ 0.8^128 per chunk-mode).

#define NSYMB   40000
#define NMODES  256
#define LEAD    20000
#define DPF     8

#define CH0     480            // exact serial DD stub length
#define NC2     8              // parallel DD chunks
#define W2      2440           // chunk body width: CH0 + NC2*W2 == 20000
#define HSPEC   480            // spec warm (starts exactly at k=20000 for c=0)
#define HFIX    128            // fix warm (bitwise collapse window)

#define NCHUNK  1000           // unwrap chunks
#define CHS     40             // NCHUNK*CHS == NSYMB

__device__ float g_su[NMODES * NC2];      // spec phi at k_sb - HFIX (fix seed)
__device__ float g_sw[NMODES * NC2];      // spec phi at k_sb - 1   (stitch, left)
__device__ float g_sv[NMODES * NC2];      // spec phi at k_end - 1  (stitch, right)
__device__ float g_noff[NMODES * NC2];    // branch integers n_c
__device__ float g_partials[NMODES * NCHUNK];
__device__ float g_boundary[NMODES * NCHUNK];

// ---- frozen DD step (fp ops identical to R11/R13) ----
__device__ __forceinline__ float dd_step(float phi, float yr, float yi, float Kv)
{
    const float QB = 0.6324555320336759f;
    const float L1 = 0.31622776601683794f;
    const float L3 = 0.9486832980505138f;
    float s, c;
    sincosf(phi, &s, &c);
    const float zr = yr * c - yi * s;
    const float zi = yr * s + yi * c;
    const float cr = copysignf((fabsf(zr) < QB) ? L1 : L3, zr);
    const float ci = copysignf((fabsf(zi) < QB) ? L1 : L3, zi);
    const float g = 2.0f * (zi * cr - zr * ci);
    return phi - Kv * g;
}

__global__ __launch_bounds__(32, 1)
void ddpll_phase_kernel(const float* __restrict__ Er,
                        const float* __restrict__ Eim,
                        const float* __restrict__ Txr,
                        const float* __restrict__ Txi,
                        const float* __restrict__ eta,
                        float*       __restrict__ out)
{
    const int b = blockIdx.x;
    const float Kv = tanhf(eta[0]);
    float* __restrict__ phi_out = out + (size_t)NSYMB * NMODES * 2;

    if (b < 8) {
        // ================= serial pilot + exact DD stub =================
        const int m = b * 32 + threadIdx.x;
        float phi = 0.0f;

        float fyr[DPF], fyi[DPF], fxr[DPF], fxi[DPF];
#pragma unroll
        for (int j = 0; j < DPF; ++j) {
            const int idx = j * NMODES + m;
            fyr[j] = Er[idx];  fyi[j] = Eim[idx];
            fxr[j] = Txr[idx]; fxi[j] = Txi[idx];
        }

        // pilot [0, LEAD): frozen XLA autodiff chain
        for (int k0 = 0; k0 < LEAD; k0 += DPF) {
#pragma unroll
            for (int j = 0; j < DPF; ++j) {
                const int k = k0 + j;
                const float yr = fyr[j], yi = fyi[j];
                const float xr = fxr[j], xi = fxi[j];
                {
                    const int idx = (k + DPF) * NMODES + m;
                    fyr[j] = Er[idx];  fyi[j] = Eim[idx];
                    fxr[j] = Txr[idx]; fxi[j] = Txi[idx];
                }
                float s, c;
                sincosf(phi, &s, &c);
                const float zr = yr * c - yi * s;
                const float zi = yr * s + yi * c;
                const float dr = zr - xr;
                const float di = zi - xi;
                const float aa = fabsf(dr), ab = fabsf(di);
                const float mx = fmaxf(aa, ab);
                const float mn = fminf(aa, ab);
                const bool  z0 = (mx == 0.0f);
                const float den1 = z0 ? 1.0f : mx;
                const float r  = mn / den1;
                const float a  = mx * sqrtf(1.0f + r * r);
                const float den2 = z0 ? 1.0f : a;
                const float t  = a + a;
                const float qr = dr / den2;
                const float qi = (-di) / den2;
                const float dbr = t * qr;
                const float dbi = t * qi;
                const float ebr = dbr * yr - dbi * yi;
                const float ebi = dbr * yi + dbi * yr;
                const float g = -(ebr * s + ebi * c);

                __stcs(&phi_out[k * NMODES + m], phi);
                phi = phi - Kv * g;
            }
        }

        // exact DD stub [LEAD, LEAD+CH0)  (CH0 multiple of DPF)
        for (int k0 = LEAD; k0 < LEAD + CH0; k0 += DPF) {
#pragma unroll
            for (int j = 0; j < DPF; ++j) {
                const int k = k0 + j;
                const float yr = fyr[j], yi = fyi[j];
                {
                    const int idx = (k + DPF) * NMODES + m;
                    fyr[j] = Er[idx];  fyi[j] = Eim[idx];
                }
                __stcs(&phi_out[k * NMODES + m], phi);
                phi = dd_step(phi, yr, yi, Kv);
            }
        }
    } else {
        // ================= speculative DD chunks (hidden under pilot) =========
        const int c = (b - 8) / 8;                    // chunk 0..NC2-1
        const int m = ((b - 8) % 8) * 32 + threadIdx.x;
        const int k_sb = LEAD + CH0 + c * W2;

        float phi = 0.0f;
        float u = 0.0f, w = 0.0f, v = 0.0f;

        // 1-deep prefetch
        int k = k_sb - HSPEC;
        float nyr = Er[k * NMODES + m];
        float nyi = Eim[k * NMODES + m];
        const int k_end = k_sb + W2;
        for (; k < k_end; ++k) {
            const float yr = nyr, yi = nyi;
            if (k + 1 < k_end) {
                const int idx = (k + 1) * NMODES + m;
                nyr = Er[idx]; nyi = Eim[idx];
            }
            if (k == k_sb - HFIX) u = phi;
            if (k == k_sb - 1)    w = phi;
            if (k == k_end - 1)   v = phi;
            phi = dd_step(phi, yr, yi, Kv);
        }
        g_su[m * NC2 + c] = u;
        g_sw[m * NC2 + c] = w;
        g_sv[m * NC2 + c] = v;
    }
}

// K2: resolve pi/2 branch integers (serial over NC2 per mode; trivial cost).
__global__ __launch_bounds__(NMODES)
void ddpll_stitch_kernel(const float* __restrict__ out)
{
    const int m = threadIdx.x;
    const float* __restrict__ phi_in = out + (size_t)NSYMB * NMODES * 2;
    const float TOP = 0.63661977236758134f;   // 2/pi

    float anchor = phi_in[(LEAD + CH0 - 1) * NMODES + m];  // exact stub end
    float n = 0.0f;
    for (int c = 0; c < NC2; ++c) {
        const float wv = g_sw[m * NC2 + c];
        n += rintf((wv - anchor) * TOP);
        g_noff[m * NC2 + c] = n;
        anchor = g_sv[m * NC2 + c];   // next comparison is spec-vs-spec
        n = 0.0f * n + n;             // carry n forward
    }
}

// K3: fix sweep — de-rotate seed, warm HFIX steps (bitwise collapse), write body.
__global__ __launch_bounds__(32, 1)
void ddpll_fix_kernel(const float* __restrict__ Er,
                      const float* __restrict__ Eim,
                      const float* __restrict__ eta,
                      float*       __restrict__ out)
{
    const int b = blockIdx.x;                  // 0 .. NC2*8-1
    const int c = b / 8;
    const int m = (b % 8) * 32 + threadIdx.x;
    const float Kv = tanhf(eta[0]);
    float* __restrict__ phi_out = out + (size_t)NSYMB * NMODES * 2;

    const int k_sb  = LEAD + CH0 + c * W2;
    const int k_beg = k_sb - HFIX;
    const int k_end = k_sb + W2;               // (HFIX+W2) % DPF == 0

    const double n = (double)g_noff[m * NC2 + c];
    float phi = (float)((double)g_su[m * NC2 + c] - n * 1.5707963267948966);

    // DPF ring over [k_beg, k_end)
    float fyr[DPF], fyi[DPF];
#pragma unroll
    for (int j = 0; j < DPF; ++j) {
        const int idx = (k_beg + j) * NMODES + m;
        fyr[j] = Er[idx]; fyi[j] = Eim[idx];
    }
    for (int k0 = k_beg; k0 < k_end; k0 += DPF) {
#pragma unroll
        for (int j = 0; j < DPF; ++j) {
            const int k = k0 + j;
            const float yr = fyr[j], yi = fyi[j];
            if (k + DPF < k_end) {
                const int idx = (k + DPF) * NMODES + m;
                fyr[j] = Er[idx]; fyi[j] = Eim[idx];
            }
            if (k >= k_sb) __stcs(&phi_out[k * NMODES + m], phi);
            phi = dd_step(phi, yr, yi, Kv);
        }
    }
}

// ---- unwrap correction: EXACT reference fp ops ----
__device__ __forceinline__ float unwrap_corr(float prev, float cur)
{
    const float PERIOD   = 1.5707963705062866f;
    const float INTERVAL = 0.5f * PERIOD;
    const float dd = cur - prev;
    if (fabsf(dd) < INTERVAL) return 0.0f;
    float r2 = fmodf(dd + INTERVAL, PERIOD);
    if (r2 < 0.0f) r2 += PERIOD;
    float ddmod = r2 - INTERVAL;
    if (ddmod == -INTERVAL && dd > 0.0f) ddmod = INTERVAL;
    return ddmod - dd;
}

__global__ __launch_bounds__(NMODES)
void ddpll_unwrap_partials(const float* __restrict__ out)
{
    const int c = blockIdx.x;
    const int m = threadIdx.x;
    const float* __restrict__ phi_in = out + (size_t)NSYMB * NMODES * 2;

    float prev = (c == 0) ? 0.0f : phi_in[(c * CHS - 1) * NMODES + m];
    g_boundary[m * NCHUNK + c] = prev;

    float sum = 0.0f;
    for (int i = 0; i < CHS; ++i) {
        const int k = c * CHS + i;
        const float cur = phi_in[k * NMODES + m];
        if (k > 0) sum += unwrap_corr(prev, cur);
        prev = cur;
    }
    g_partials[m * NCHUNK + c] = sum;
}

__global__ __launch_bounds__(NMODES)
void ddpll_unwrap_scan()
{
    const int m = threadIdx.x;
    float run = 0.0f;
    for (int c = 0; c < NCHUNK; ++c) {
        const float v = g_partials[m * NCHUNK + c];
        g_partials[m * NCHUNK + c] = run;
        run += v;
    }
}

__global__ __launch_bounds__(NMODES)
void ddpll_apply_kernel(const float* __restrict__ Er,
                        const float* __restrict__ Eim,
                        float*       __restrict__ out)
{
    const int c = blockIdx.x;
    const int m = threadIdx.x;
    float* __restrict__ theta_io = out + (size_t)NSYMB * NMODES * 2;
    float2* __restrict__ eo_out  = reinterpret_cast<float2*>(out);

    float C    = g_partials[m * NCHUNK + c];
    float prev = g_boundary[m * NCHUNK + c];

    for (int i = 0; i < CHS; ++i) {
        const int k = c * CHS + i;
        const float cur = theta_io[k * NMODES + m];
        if (k > 0) C += unwrap_corr(prev, cur);
        prev = cur;

        const float th = cur + C;
        __stcs(&theta_io[k * NMODES + m], th);

        const float yr = Er[k * NMODES + m];
        const float yi = Eim[k * NMODES + m];
        float s, cc;
        __sincosf(th, &s, &cc);
        float2 eo;
        eo.x = yr * cc - yi * s;
        eo.y = yr * s + yi * cc;
        __stcs(&eo_out[k * NMODES + m], eo);
    }
}

extern "C" void kernel_launch(void* const* d_in, const int* in_sizes, int n_in,
                              void* d_out, int out_size)
{
    const float* Er  = (const float*)d_in[0];
    const float* Eim = (const float*)d_in[1];
    const float* Txr = (const float*)d_in[2];
    const float* Txi = (const float*)d_in[3];
    const float* eta = (const float*)d_in[4];
    float* out = (float*)d_out;

    ddpll_phase_kernel<<<8 + NC2 * 8, 32>>>(Er, Eim, Txr, Txi, eta, out);
    ddpll_stitch_kernel<<<1, NMODES>>>(out);
    ddpll_fix_kernel<<<NC2 * 8, 32>>>(Er, Eim, eta, out);
    ddpll_unwrap_partials<<<NCHUNK, NMODES>>>(out);
    ddpll_unwrap_scan<<<1, NMODES>>>();
    ddpll_apply_kernel<<<NCHUNK, NMODES>>>(Er, Eim, out);
}

// round 15
// speedup vs baseline: 5.3774x; 1.6827x over previous
#include <cuda_runtime.h>
#include <math.h>

// DDPLL — pilot AND DD regions chunk-parallel via speculate/stitch/fix.
//
//  K1 phase:  blocks 0-7    serial exact pilot chunk 0  [0, 2000)
//             blocks 8-79   speculative pilot chunks 1-9 (warm 2000 + body 2000)
//             blocks 80-143 speculative DD chunks (warm 480 + body 2440)
//  K2 stitchP: resolve 2*pi branch ints for pilot chunks (pilot map is 2pi-periodic)
//  K3 fixP:    de-rotate seed, warm 512 (bitwise collapse), write body; last chunk
//              appends the 480-step exact DD stub [20000, 20480)
//  K4 stitchDD: resolve pi/2 branch ints (DD slicer symmetry), anchor = stub end
//  K5 fixDD:   as R14 (warm 128 + body 2440)
//  K6-K8:      unwrap partials / scan / apply+rotate (R13/R14-proven)
//
// FROZEN: the per-step fp op sequences (libdevice sincosf; XLA autodiff chain in
// pilot; QAM slicer in DD) — validated bitwise/gate-safe in R5/R7/R11/R13/R14.
// Collapse mechanism (R14-validated): both chains iterate the SAME deterministic
// fp map; average contraction (pilot E[lambda]~-0.03, DD ~-0.22) drives the gap
// to ulp scale where rounding quantization produces exact collision — absorbing.
// Pilot warm 2000 (+512 fix-warm) gives mean contraction e^-75: branch resolution
// and collision are overwhelmingly safe.

#define NSYMB   40000
#define NMODES  256
#define LEAD    20000
#define DPF     8

// pilot chunking
#define NP      10            // pilot chunks, width WP each
#define WP      2000          // NP*WP == LEAD
#define HP      2000          // pilot spec warm
#define HFIXP   512           // pilot fix warm (512+2000 divisible by DPF)

// DD chunking (R14-proven)
#define CH0     480           // exact DD stub (appended to last pilot fix)
#define NC2     8
#define W2      2440          // CH0 + NC2*W2 == 20000
#define HSPEC   480
#define HFIX    128           // 128+2440 divisible by DPF

// unwrap
#define NCHUNK  1000
#define CHS     40

__device__ float g_suP[NMODES * NP];     // pilot spec phi at k_sb-HFIXP
__device__ float g_swP[NMODES * NP];     // pilot spec phi at k_sb-1
__device__ float g_svP[NMODES * NP];     // pilot spec phi at k_end-1
__device__ float g_noffP[NMODES * NP];   // pilot branch ints (units of 2*pi)
__device__ float g_su[NMODES * NC2];
__device__ float g_sw[NMODES * NC2];
__device__ float g_sv[NMODES * NC2];
__device__ float g_noff[NMODES * NC2];   // DD branch ints (units of pi/2)
__device__ float g_partials[NMODES * NCHUNK];
__device__ float g_boundary[NMODES * NCHUNK];

// ---- frozen pilot step (XLA autodiff chain, fp ops identical to R11-R14) ----
__device__ __forceinline__ float pilot_step(float phi, float yr, float yi,
                                            float xr, float xi, float Kv)
{
    float s, c;
    sincosf(phi, &s, &c);
    const float zr = yr * c - yi * s;
    const float zi = yr * s + yi * c;
    const float dr = zr - xr;
    const float di = zi - xi;
    const float aa = fabsf(dr), ab = fabsf(di);
    const float mx = fmaxf(aa, ab);
    const float mn = fminf(aa, ab);
    const bool  z0 = (mx == 0.0f);
    const float den1 = z0 ? 1.0f : mx;
    const float r  = mn / den1;
    const float a  = mx * sqrtf(1.0f + r * r);
    const float den2 = z0 ? 1.0f : a;
    const float t  = a + a;
    const float qr = dr / den2;
    const float qi = (-di) / den2;
    const float dbr = t * qr;
    const float dbi = t * qi;
    const float ebr = dbr * yr - dbi * yi;
    const float ebi = dbr * yi + dbi * yr;
    const float g = -(ebr * s + ebi * c);
    return phi - Kv * g;
}

// ---- frozen DD step ----
__device__ __forceinline__ float dd_step(float phi, float yr, float yi, float Kv)
{
    const float QB = 0.6324555320336759f;
    const float L1 = 0.31622776601683794f;
    const float L3 = 0.9486832980505138f;
    float s, c;
    sincosf(phi, &s, &c);
    const float zr = yr * c - yi * s;
    const float zi = yr * s + yi * c;
    const float cr = copysignf((fabsf(zr) < QB) ? L1 : L3, zr);
    const float ci = copysignf((fabsf(zi) < QB) ? L1 : L3, zi);
    const float g = 2.0f * (zi * cr - zr * ci);
    return phi - Kv * g;
}

__global__ __launch_bounds__(32, 1)
void ddpll_phase_kernel(const float* __restrict__ Er,
                        const float* __restrict__ Eim,
                        const float* __restrict__ Txr,
                        const float* __restrict__ Txi,
                        const float* __restrict__ eta,
                        float*       __restrict__ out)
{
    const int b = blockIdx.x;
    const float Kv = tanhf(eta[0]);
    float* __restrict__ phi_out = out + (size_t)NSYMB * NMODES * 2;

    if (b < 8) {
        // ---- serial exact pilot chunk 0: [0, WP) ----
        const int m = b * 32 + threadIdx.x;
        float phi = 0.0f;
        float fyr[DPF], fyi[DPF], fxr[DPF], fxi[DPF];
#pragma unroll
        for (int j = 0; j < DPF; ++j) {
            const int idx = j * NMODES + m;
            fyr[j] = Er[idx];  fyi[j] = Eim[idx];
            fxr[j] = Txr[idx]; fxi[j] = Txi[idx];
        }
        for (int k0 = 0; k0 < WP; k0 += DPF) {
#pragma unroll
            for (int j = 0; j < DPF; ++j) {
                const int k = k0 + j;
                const float yr = fyr[j], yi = fyi[j];
                const float xr = fxr[j], xi = fxi[j];
                {
                    const int idx = (k + DPF) * NMODES + m;
                    fyr[j] = Er[idx];  fyi[j] = Eim[idx];
                    fxr[j] = Txr[idx]; fxi[j] = Txi[idx];
                }
                __stcs(&phi_out[k * NMODES + m], phi);
                phi = pilot_step(phi, yr, yi, xr, xi, Kv);
            }
        }
    } else if (b < 80) {
        // ---- speculative pilot chunks c = 1..9 ----
        const int idx0 = b - 8;
        const int c = idx0 / 8 + 1;
        const int m = (idx0 % 8) * 32 + threadIdx.x;
        const int k_sb  = c * WP;
        const int k_end = k_sb + WP;

        float phi = 0.0f;
        float u = 0.0f, w = 0.0f, v = 0.0f;

        int k = k_sb - HP;
        float nyr = Er[k * NMODES + m],  nyi = Eim[k * NMODES + m];
        float nxr = Txr[k * NMODES + m], nxi = Txi[k * NMODES + m];
        for (; k < k_end; ++k) {
            const float yr = nyr, yi = nyi, xr = nxr, xi = nxi;
            if (k + 1 < k_end) {
                const int idx = (k + 1) * NMODES + m;
                nyr = Er[idx];  nyi = Eim[idx];
                nxr = Txr[idx]; nxi = Txi[idx];
            }
            if (k == k_sb - HFIXP) u = phi;
            if (k == k_sb - 1)     w = phi;
            if (k == k_end - 1)    v = phi;
            phi = pilot_step(phi, yr, yi, xr, xi, Kv);
        }
        g_suP[m * NP + c] = u;
        g_swP[m * NP + c] = w;
        g_svP[m * NP + c] = v;
    } else {
        // ---- speculative DD chunks (R14) ----
        const int idx0 = b - 80;
        const int c = idx0 / 8;
        const int m = (idx0 % 8) * 32 + threadIdx.x;
        const int k_sb  = LEAD + CH0 + c * W2;
        const int k_end = k_sb + W2;

        float phi = 0.0f;
        float u = 0.0f, w = 0.0f, v = 0.0f;

        int k = k_sb - HSPEC;
        float nyr = Er[k * NMODES + m], nyi = Eim[k * NMODES + m];
        for (; k < k_end; ++k) {
            const float yr = nyr, yi = nyi;
            if (k + 1 < k_end) {
                const int idx = (k + 1) * NMODES + m;
                nyr = Er[idx]; nyi = Eim[idx];
            }
            if (k == k_sb - HFIX) u = phi;
            if (k == k_sb - 1)    w = phi;
            if (k == k_end - 1)   v = phi;
            phi = dd_step(phi, yr, yi, Kv);
        }
        g_su[m * NC2 + c] = u;
        g_sw[m * NC2 + c] = w;
        g_sv[m * NC2 + c] = v;
    }
}

// K2: pilot stitch — branch ints in units of 2*pi (pilot map 2pi-periodic).
__global__ __launch_bounds__(NMODES)
void ddpll_stitchP_kernel(const float* __restrict__ out)
{
    const int m = threadIdx.x;
    const float* __restrict__ phi_in = out + (size_t)NSYMB * NMODES * 2;
    const float INV2PI = 0.15915494309189535f;

    float anchor = phi_in[(WP - 1) * NMODES + m];   // exact serial chunk end
    float n = 0.0f;
    for (int c = 1; c < NP; ++c) {
        const float wv = g_swP[m * NP + c];
        n += rintf((wv - anchor) * INV2PI);
        g_noffP[m * NP + c] = n;
        anchor = g_svP[m * NP + c];
    }
}

// K3: pilot fix — de-rotate by n*2pi, warm HFIXP (collapse), write body.
// Last chunk (c == NP-1) appends the exact DD stub [LEAD, LEAD+CH0).
__global__ __launch_bounds__(32, 1)
void ddpll_fixP_kernel(const float* __restrict__ Er,
                       const float* __restrict__ Eim,
                       const float* __restrict__ Txr,
                       const float* __restrict__ Txi,
                       const float* __restrict__ eta,
                       float*       __restrict__ out)
{
    const int b = blockIdx.x;                 // 0 .. (NP-1)*8 - 1
    const int c = b / 8 + 1;
    const int m = (b % 8) * 32 + threadIdx.x;
    const float Kv = tanhf(eta[0]);
    float* __restrict__ phi_out = out + (size_t)NSYMB * NMODES * 2;

    const int k_sb  = c * WP;
    const int k_beg = k_sb - HFIXP;
    const int k_end = k_sb + WP;              // (HFIXP+WP) % DPF == 0

    const double n = (double)g_noffP[m * NP + c];
    float phi = (float)((double)g_suP[m * NP + c] - n * 6.283185307179586);

    float fyr[DPF], fyi[DPF], fxr[DPF], fxi[DPF];
#pragma unroll
    for (int j = 0; j < DPF; ++j) {
        const int idx = (k_beg + j) * NMODES + m;
        fyr[j] = Er[idx];  fyi[j] = Eim[idx];
        fxr[j] = Txr[idx]; fxi[j] = Txi[idx];
    }
    for (int k0 = k_beg; k0 < k_end; k0 += DPF) {
#pragma unroll
        for (int j = 0; j < DPF; ++j) {
            const int k = k0 + j;
            const float yr = fyr[j], yi = fyi[j];
            const float xr = fxr[j], xi = fxi[j];
            if (k + DPF < k_end) {
                const int idx = (k + DPF) * NMODES + m;
                fyr[j] = Er[idx];  fyi[j] = Eim[idx];
                fxr[j] = Txr[idx]; fxi[j] = Txi[idx];
            }
            if (k >= k_sb) __stcs(&phi_out[k * NMODES + m], phi);
            phi = pilot_step(phi, yr, yi, xr, xi, Kv);
        }
    }

    if (c == NP - 1) {
        // exact DD stub [LEAD, LEAD+CH0) — fresh ring, dd_step
        float syr[DPF], syi[DPF];
#pragma unroll
        for (int j = 0; j < DPF; ++j) {
            const int idx = (LEAD + j) * NMODES + m;
            syr[j] = Er[idx]; syi[j] = Eim[idx];
        }
        for (int k0 = LEAD; k0 < LEAD + CH0; k0 += DPF) {
#pragma unroll
            for (int j = 0; j < DPF; ++j) {
                const int k = k0 + j;
                const float yr = syr[j], yi = syi[j];
                if (k + DPF < LEAD + CH0) {
                    const int idx = (k + DPF) * NMODES + m;
                    syr[j] = Er[idx]; syi[j] = Eim[idx];
                }
                __stcs(&phi_out[k * NMODES + m], phi);
                phi = dd_step(phi, yr, yi, Kv);
            }
        }
    }
}

// K4: DD stitch — branch ints in units of pi/2 (slicer symmetry). R14-proven.
__global__ __launch_bounds__(NMODES)
void ddpll_stitchDD_kernel(const float* __restrict__ out)
{
    const int m = threadIdx.x;
    const float* __restrict__ phi_in = out + (size_t)NSYMB * NMODES * 2;
    const float TOP = 0.63661977236758134f;   // 2/pi

    float anchor = phi_in[(LEAD + CH0 - 1) * NMODES + m];
    float n = 0.0f;
    for (int c = 0; c < NC2; ++c) {
        const float wv = g_sw[m * NC2 + c];
        n += rintf((wv - anchor) * TOP);
        g_noff[m * NC2 + c] = n;
        anchor = g_sv[m * NC2 + c];
    }
}

// K5: DD fix (R14-proven).
__global__ __launch_bounds__(32, 1)
void ddpll_fixDD_kernel(const float* __restrict__ Er,
                        const float* __restrict__ Eim,
                        const float* __restrict__ eta,
                        float*       __restrict__ out)
{
    const int b = blockIdx.x;
    const int c = b / 8;
    const int m = (b % 8) * 32 + threadIdx.x;
    const float Kv = tanhf(eta[0]);
    float* __restrict__ phi_out = out + (size_t)NSYMB * NMODES * 2;

    const int k_sb  = LEAD + CH0 + c * W2;
    const int k_beg = k_sb - HFIX;
    const int k_end = k_sb + W2;

    const double n = (double)g_noff[m * NC2 + c];
    float phi = (float)((double)g_su[m * NC2 + c] - n * 1.5707963267948966);

    float fyr[DPF], fyi[DPF];
#pragma unroll
    for (int j = 0; j < DPF; ++j) {
        const int idx = (k_beg + j) * NMODES + m;
        fyr[j] = Er[idx]; fyi[j] = Eim[idx];
    }
    for (int k0 = k_beg; k0 < k_end; k0 += DPF) {
#pragma unroll
        for (int j = 0; j < DPF; ++j) {
            const int k = k0 + j;
            const float yr = fyr[j], yi = fyi[j];
            if (k + DPF < k_end) {
                const int idx = (k + DPF) * NMODES + m;
                fyr[j] = Er[idx]; fyi[j] = Eim[idx];
            }
            if (k >= k_sb) __stcs(&phi_out[k * NMODES + m], phi);
            phi = dd_step(phi, yr, yi, Kv);
        }
    }
}

// ---- unwrap (exact reference fp ops) ----
__device__ __forceinline__ float unwrap_corr(float prev, float cur)
{
    const float PERIOD   = 1.5707963705062866f;
    const float INTERVAL = 0.5f * PERIOD;
    const float dd = cur - prev;
    if (fabsf(dd) < INTERVAL) return 0.0f;
    float r2 = fmodf(dd + INTERVAL, PERIOD);
    if (r2 < 0.0f) r2 += PERIOD;
    float ddmod = r2 - INTERVAL;
    if (ddmod == -INTERVAL && dd > 0.0f) ddmod = INTERVAL;
    return ddmod - dd;
}

__global__ __launch_bounds__(NMODES)
void ddpll_unwrap_partials(const float* __restrict__ out)
{
    const int c = blockIdx.x;
    const int m = threadIdx.x;
    const float* __restrict__ phi_in = out + (size_t)NSYMB * NMODES * 2;

    float prev = (c == 0) ? 0.0f : phi_in[(c * CHS - 1) * NMODES + m];
    g_boundary[m * NCHUNK + c] = prev;

    float sum = 0.0f;
    for (int i = 0; i < CHS; ++i) {
        const int k = c * CHS + i;
        const float cur = phi_in[k * NMODES + m];
        if (k > 0) sum += unwrap_corr(prev, cur);
        prev = cur;
    }
    g_partials[m * NCHUNK + c] = sum;
}

__global__ __launch_bounds__(NMODES)
void ddpll_unwrap_scan()
{
    const int m = threadIdx.x;
    float run = 0.0f;
    for (int c = 0; c < NCHUNK; ++c) {
        const float v = g_partials[m * NCHUNK + c];
        g_partials[m * NCHUNK + c] = run;
        run += v;
    }
}

__global__ __launch_bounds__(NMODES)
void ddpll_apply_kernel(const float* __restrict__ Er,
                        const float* __restrict__ Eim,
                        float*       __restrict__ out)
{
    const int c = blockIdx.x;
    const int m = threadIdx.x;
    float* __restrict__ theta_io = out + (size_t)NSYMB * NMODES * 2;
    float2* __restrict__ eo_out  = reinterpret_cast<float2*>(out);

    float C    = g_partials[m * NCHUNK + c];
    float prev = g_boundary[m * NCHUNK + c];

    for (int i = 0; i < CHS; ++i) {
        const int k = c * CHS + i;
        const float cur = theta_io[k * NMODES + m];
        if (k > 0) C += unwrap_corr(prev, cur);
        prev = cur;

        const float th = cur + C;
        __stcs(&theta_io[k * NMODES + m], th);

        const float yr = Er[k * NMODES + m];
        const float yi = Eim[k * NMODES + m];
        float s, cc;
        __sincosf(th, &s, &cc);
        float2 eo;
        eo.x = yr * cc - yi * s;
        eo.y = yr * s + yi * cc;
        __stcs(&eo_out[k * NMODES + m], eo);
    }
}

extern "C" void kernel_launch(void* const* d_in, const int* in_sizes, int n_in,
                              void* d_out, int out_size)
{
    const float* Er  = (const float*)d_in[0];
    const float* Eim = (const float*)d_in[1];
    const float* Txr = (const float*)d_in[2];
    const float* Txi = (const float*)d_in[3];
    const float* eta = (const float*)d_in[4];
    float* out = (float*)d_out;

    ddpll_phase_kernel<<<8 + (NP - 1) * 8 + NC2 * 8, 32>>>(Er, Eim, Txr, Txi, eta, out);
    ddpll_stitchP_kernel<<<1, NMODES>>>(out);
    ddpll_fixP_kernel<<<(NP - 1) * 8, 32>>>(Er, Eim, Txr, Txi, eta, out);
    ddpll_stitchDD_kernel<<<1, NMODES>>>(out);
    ddpll_fixDD_kernel<<<NC2 * 8, 32>>>(Er, Eim, eta, out);
    ddpll_unwrap_partials<<<NCHUNK, NMODES>>>(out);
    ddpll_unwrap_scan<<<1, NMODES>>>();
    ddpll_apply_kernel<<<NCHUNK, NMODES>>>(Er, Eim, out);
}

// round 16
// speedup vs baseline: 7.9232x; 1.4734x over previous
#include <cuda_runtime.h>
#include <math.h>

// DDPLL — fully chunk-parallel via speculate/stitch/fix (R14/R15-validated), R16:
// narrower chunks + sub-chunked DD fix + 4-warps-per-block SMSP packing.
//
//  K1 spec : 448 warp-items (one chain per SMSP):
//            items 0-319  pilot chunks c=0..39 (warm 1200, body 500; chunks whose
//                         warm would start <0 clamp to the exact IC phi(0)=0)
//            items 320-447 DD chunks c=0..15 (warm 480, body 1220; 2 fix seeds)
//  K2 stitchP : 2*pi branch ints per pilot chunk (chained boundary rints)
//  K3 fixP    : warm 512 (bitwise collapse) + body 500; last chunk appends the
//               exact 480-step DD stub [20000,20480)
//  K4 stitchDD: pi/2 branch ints per DD chunk (anchor = stub end)
//  K5 fixDD   : 2 half-chunks per DD chunk: warm 128 + body 610
//  K6-K8      : unwrap partials / scan / apply+rotate (proven; finer chunks)
//
// FROZEN: per-step fp op sequences (libdevice sincosf; XLA autodiff chain in
// pilot; QAM slicer in DD) — gate-safe across R5/R7/R11/R13/R14/R15.
// Collapse: both chains iterate the SAME deterministic fp map; contraction
// (pilot E[lambda]~-0.03/step, DD ~-0.22/step) + rounding quantization =>
// exact collision, absorbing. Pilot total warm 1712 steps => mean e^-51.

#define NSYMB   40000
#define NMODES  256
#define LEAD    20000

// pilot chunking
#define NPS     40
#define WPS     500            // NPS*WPS == LEAD
#define HP      1200           // pilot spec warm
#define HFIXP   512            // pilot fix warm

// DD chunking
#define CH0     480            // exact DD stub after pilot fix
#define NC      16
#define W2      1220           // CH0 + NC*W2 == 20000
#define WFD     610            // DD fix half-chunk width (2*WFD == W2)
#define HSPEC   480
#define HFIX    128

// unwrap
#define NCHUNK  2000
#define CHS     20             // NCHUNK*CHS == NSYMB

__device__ float g_suP[NMODES * NPS];
__device__ float g_swP[NMODES * NPS];
__device__ float g_svP[NMODES * NPS];
__device__ float g_noffP[NMODES * NPS];
__device__ float g_suD[NMODES * NC * 2];   // two fix seeds per DD chunk
__device__ float g_swD[NMODES * NC];
__device__ float g_svD[NMODES * NC];
__device__ float g_noffD[NMODES * NC];
__device__ float g_partials[NMODES * NCHUNK];
__device__ float g_boundary[NMODES * NCHUNK];

// ---- frozen pilot step (XLA autodiff chain) ----
__device__ __forceinline__ float pilot_step(float phi, float yr, float yi,
                                            float xr, float xi, float Kv)
{
    float s, c;
    sincosf(phi, &s, &c);
    const float zr = yr * c - yi * s;
    const float zi = yr * s + yi * c;
    const float dr = zr - xr;
    const float di = zi - xi;
    const float aa = fabsf(dr), ab = fabsf(di);
    const float mx = fmaxf(aa, ab);
    const float mn = fminf(aa, ab);
    const bool  z0 = (mx == 0.0f);
    const float den1 = z0 ? 1.0f : mx;
    const float r  = mn / den1;
    const float a  = mx * sqrtf(1.0f + r * r);
    const float den2 = z0 ? 1.0f : a;
    const float t  = a + a;
    const float qr = dr / den2;
    const float qi = (-di) / den2;
    const float dbr = t * qr;
    const float dbi = t * qi;
    const float ebr = dbr * yr - dbi * yi;
    const float ebi = dbr * yi + dbi * yr;
    const float g = -(ebr * s + ebi * c);
    return phi - Kv * g;
}

// ---- frozen DD step ----
__device__ __forceinline__ float dd_step(float phi, float yr, float yi, float Kv)
{
    const float QB = 0.6324555320336759f;
    const float L1 = 0.31622776601683794f;
    const float L3 = 0.9486832980505138f;
    float s, c;
    sincosf(phi, &s, &c);
    const float zr = yr * c - yi * s;
    const float zi = yr * s + yi * c;
    const float cr = copysignf((fabsf(zr) < QB) ? L1 : L3, zr);
    const float ci = copysignf((fabsf(zi) < QB) ? L1 : L3, zi);
    const float g = 2.0f * (zi * cr - zr * ci);
    return phi - Kv * g;
}

// K1: all speculative chains. 4 warp-items per 128-thread block (one per SMSP).
__global__ __launch_bounds__(128, 1)
void ddpll_spec_kernel(const float* __restrict__ Er,
                       const float* __restrict__ Eim,
                       const float* __restrict__ Txr,
                       const float* __restrict__ Txi,
                       const float* __restrict__ eta)
{
    const int item = blockIdx.x * 4 + (threadIdx.x >> 5);
    const int lane = threadIdx.x & 31;
    const float Kv = tanhf(eta[0]);

    if (item < NPS * 8) {
        // ---- pilot spec chunk ----
        const int c = item >> 3;
        const int m = (item & 7) * 32 + lane;
        const int k_sb  = c * WPS;
        const int k_end = k_sb + WPS;
        int kw = k_sb - HP;
        if (kw < 0) kw = 0;                 // clamped => exact orbit from phi(0)=0

        float phi = 0.0f;
        float u = 0.0f, w = 0.0f, v = 0.0f;

        int k = kw;
        float nyr = Er[k * NMODES + m],  nyi = Eim[k * NMODES + m];
        float nxr = Txr[k * NMODES + m], nxi = Txi[k * NMODES + m];
        for (; k < k_end; ++k) {
            const float yr = nyr, yi = nyi, xr = nxr, xi = nxi;
            if (k + 1 < k_end) {
                const int idx = (k + 1) * NMODES + m;
                nyr = Er[idx];  nyi = Eim[idx];
                nxr = Txr[idx]; nxi = Txi[idx];
            }
            if (k == k_sb - HFIXP) u = phi;
            if (k == k_sb - 1)     w = phi;
            if (k == k_end - 1)    v = phi;
            phi = pilot_step(phi, yr, yi, xr, xi, Kv);
        }
        g_suP[m * NPS + c] = u;
        g_swP[m * NPS + c] = w;
        g_svP[m * NPS + c] = v;
    } else {
        // ---- DD spec chunk ----
        const int t = item - NPS * 8;
        const int c = t >> 3;
        const int m = (t & 7) * 32 + lane;
        const int k_sb  = LEAD + CH0 + c * W2;
        const int k_end = k_sb + W2;

        float phi = 0.0f;
        float u0 = 0.0f, u1 = 0.0f, w = 0.0f, v = 0.0f;

        int k = k_sb - HSPEC;
        float nyr = Er[k * NMODES + m], nyi = Eim[k * NMODES + m];
        for (; k < k_end; ++k) {
            const float yr = nyr, yi = nyi;
            if (k + 1 < k_end) {
                const int idx = (k + 1) * NMODES + m;
                nyr = Er[idx]; nyi = Eim[idx];
            }
            if (k == k_sb - HFIX)       u0 = phi;
            if (k == k_sb + WFD - HFIX) u1 = phi;
            if (k == k_sb - 1)          w  = phi;
            if (k == k_end - 1)         v  = phi;
            phi = dd_step(phi, yr, yi, Kv);
        }
        g_suD[(m * NC + c) * 2 + 0] = u0;
        g_suD[(m * NC + c) * 2 + 1] = u1;
        g_swD[m * NC + c] = w;
        g_svD[m * NC + c] = v;
    }
}

// K2: pilot stitch — chained 2*pi branch ints.
__global__ __launch_bounds__(NMODES)
void ddpll_stitchP_kernel()
{
    const int m = threadIdx.x;
    const float INV2PI = 0.15915494309189535f;

    float anchor = g_svP[m * NPS + 0];     // chunk 0 is exact (clamped warm)
    float n = 0.0f;
    g_noffP[m * NPS + 0] = 0.0f;
    for (int c = 1; c < NPS; ++c) {
        const float wv = g_swP[m * NPS + c];
        n += rintf((wv - anchor) * INV2PI);
        g_noffP[m * NPS + c] = n;
        anchor = g_svP[m * NPS + c];
    }
}

// K3: pilot fix — de-rotate seed, warm HFIXP, write body. Last chunk appends stub.
__global__ __launch_bounds__(128, 1)
void ddpll_fixP_kernel(const float* __restrict__ Er,
                       const float* __restrict__ Eim,
                       const float* __restrict__ Txr,
                       const float* __restrict__ Txi,
                       const float* __restrict__ eta,
                       float*       __restrict__ out)
{
    const int item = blockIdx.x * 4 + (threadIdx.x >> 5);
    const int lane = threadIdx.x & 31;
    const int c = item >> 3;
    const int m = (item & 7) * 32 + lane;
    const float Kv = tanhf(eta[0]);
    float* __restrict__ phi_out = out + (size_t)NSYMB * NMODES * 2;

    const int k_sb  = c * WPS;
    const int k_end = k_sb + WPS;
    int kb = k_sb - HFIXP;

    float phi;
    if (kb <= 0) {                          // chunks 0,1: exact from the true IC
        kb = 0;
        phi = 0.0f;
    } else {
        const double n = (double)g_noffP[m * NPS + c];
        phi = (float)((double)g_suP[m * NPS + c] - n * 6.283185307179586);
    }

    int k = kb;
    float nyr = Er[k * NMODES + m],  nyi = Eim[k * NMODES + m];
    float nxr = Txr[k * NMODES + m], nxi = Txi[k * NMODES + m];
    for (; k < k_end; ++k) {
        const float yr = nyr, yi = nyi, xr = nxr, xi = nxi;
        if (k + 1 < k_end) {
            const int idx = (k + 1) * NMODES + m;
            nyr = Er[idx];  nyi = Eim[idx];
            nxr = Txr[idx]; nxi = Txi[idx];
        }
        if (k >= k_sb) __stcs(&phi_out[k * NMODES + m], phi);
        phi = pilot_step(phi, yr, yi, xr, xi, Kv);
    }

    if (c == NPS - 1) {
        // exact DD stub [LEAD, LEAD+CH0)
        int kk = LEAD;
        float syr = Er[kk * NMODES + m], syi = Eim[kk * NMODES + m];
        for (; kk < LEAD + CH0; ++kk) {
            const float yr = syr, yi = syi;
            if (kk + 1 < LEAD + CH0) {
                const int idx = (kk + 1) * NMODES + m;
                syr = Er[idx]; syi = Eim[idx];
            }
            __stcs(&phi_out[kk * NMODES + m], phi);
            phi = dd_step(phi, yr, yi, Kv);
        }
    }
}

// K4: DD stitch — pi/2 branch ints; anchor = exact stub end.
__global__ __launch_bounds__(NMODES)
void ddpll_stitchDD_kernel(const float* __restrict__ out)
{
    const int m = threadIdx.x;
    const float* __restrict__ phi_in = out + (size_t)NSYMB * NMODES * 2;
    const float TOP = 0.63661977236758134f;   // 2/pi

    float anchor = phi_in[(LEAD + CH0 - 1) * NMODES + m];
    float n = 0.0f;
    for (int c = 0; c < NC; ++c) {
        const float wv = g_swD[m * NC + c];
        n += rintf((wv - anchor) * TOP);
        g_noffD[m * NC + c] = n;
        anchor = g_svD[m * NC + c];
    }
}

// K5: DD fix — two half-chunks per DD chunk.
__global__ __launch_bounds__(128, 1)
void ddpll_fixDD_kernel(const float* __restrict__ Er,
                        const float* __restrict__ Eim,
                        const float* __restrict__ eta,
                        float*       __restrict__ out)
{
    const int item = blockIdx.x * 4 + (threadIdx.x >> 5);   // 0 .. NC*2*8-1
    const int lane = threadIdx.x & 31;
    const int c = item >> 4;              // DD chunk
    const int r = item & 15;
    const int h = r >> 3;                 // half 0/1
    const int m = (r & 7) * 32 + lane;
    const float Kv = tanhf(eta[0]);
    float* __restrict__ phi_out = out + (size_t)NSYMB * NMODES * 2;

    const int p     = LEAD + CH0 + c * W2 + h * WFD;
    const int k_beg = p - HFIX;
    const int k_end = p + WFD;

    const double n = (double)g_noffD[m * NC + c];
    float phi = (float)((double)g_suD[(m * NC + c) * 2 + h] - n * 1.5707963267948966);

    int k = k_beg;
    float nyr = Er[k * NMODES + m], nyi = Eim[k * NMODES + m];
    for (; k < k_end; ++k) {
        const float yr = nyr, yi = nyi;
        if (k + 1 < k_end) {
            const int idx = (k + 1) * NMODES + m;
            nyr = Er[idx]; nyi = Eim[idx];
        }
        if (k >= p) __stcs(&phi_out[k * NMODES + m], phi);
        phi = dd_step(phi, yr, yi, Kv);
    }
}

// ---- unwrap (exact reference fp ops) ----
__device__ __forceinline__ float unwrap_corr(float prev, float cur)
{
    const float PERIOD   = 1.5707963705062866f;
    const float INTERVAL = 0.5f * PERIOD;
    const float dd = cur - prev;
    if (fabsf(dd) < INTERVAL) return 0.0f;
    float r2 = fmodf(dd + INTERVAL, PERIOD);
    if (r2 < 0.0f) r2 += PERIOD;
    float ddmod = r2 - INTERVAL;
    if (ddmod == -INTERVAL && dd > 0.0f) ddmod = INTERVAL;
    return ddmod - dd;
}

__global__ __launch_bounds__(NMODES)
void ddpll_unwrap_partials(const float* __restrict__ out)
{
    const int c = blockIdx.x;
    const int m = threadIdx.x;
    const float* __restrict__ phi_in = out + (size_t)NSYMB * NMODES * 2;

    float prev = (c == 0) ? 0.0f : phi_in[(c * CHS - 1) * NMODES + m];
    g_boundary[m * NCHUNK + c] = prev;

    float sum = 0.0f;
    for (int i = 0; i < CHS; ++i) {
        const int k = c * CHS + i;
        const float cur = phi_in[k * NMODES + m];
        if (k > 0) sum += unwrap_corr(prev, cur);
        prev = cur;
    }
    g_partials[m * NCHUNK + c] = sum;
}

__global__ __launch_bounds__(NMODES)
void ddpll_unwrap_scan()
{
    const int m = threadIdx.x;
    float run = 0.0f;
    for (int c = 0; c < NCHUNK; ++c) {
        const float v = g_partials[m * NCHUNK + c];
        g_partials[m * NCHUNK + c] = run;
        run += v;
    }
}

__global__ __launch_bounds__(NMODES)
void ddpll_apply_kernel(const float* __restrict__ Er,
                        const float* __restrict__ Eim,
                        float*       __restrict__ out)
{
    const int c = blockIdx.x;
    const int m = threadIdx.x;
    float* __restrict__ theta_io = out + (size_t)NSYMB * NMODES * 2;
    float2* __restrict__ eo_out  = reinterpret_cast<float2*>(out);

    float C    = g_partials[m * NCHUNK + c];
    float prev = g_boundary[m * NCHUNK + c];

    for (int i = 0; i < CHS; ++i) {
        const int k = c * CHS + i;
        const float cur = theta_io[k * NMODES + m];
        if (k > 0) C += unwrap_corr(prev, cur);
        prev = cur;

        const float th = cur + C;
        __stcs(&theta_io[k * NMODES + m], th);

        const float yr = Er[k * NMODES + m];
        const float yi = Eim[k * NMODES + m];
        float s, cc;
        __sincosf(th, &s, &cc);
        float2 eo;
        eo.x = yr * cc - yi * s;
        eo.y = yr * s + yi * cc;
        __stcs(&eo_out[k * NMODES + m], eo);
    }
}

extern "C" void kernel_launch(void* const* d_in, const int* in_sizes, int n_in,
                              void* d_out, int out_size)
{
    const float* Er  = (const float*)d_in[0];
    const float* Eim = (const float*)d_in[1];
    const float* Txr = (const float*)d_in[2];
    const float* Txi = (const float*)d_in[3];
    const float* eta = (const float*)d_in[4];
    float* out = (float*)d_out;

    ddpll_spec_kernel<<<(NPS * 8 + NC * 8) / 4, 128>>>(Er, Eim, Txr, Txi, eta);
    ddpll_stitchP_kernel<<<1, NMODES>>>();
    ddpll_fixP_kernel<<<NPS * 8 / 4, 128>>>(Er, Eim, Txr, Txi, eta, out);
    ddpll_stitchDD_kernel<<<1, NMODES>>>(out);
    ddpll_fixDD_kernel<<<NC * 2 * 8 / 4, 128>>>(Er, Eim, eta, out);
    ddpll_unwrap_partials<<<NCHUNK, NMODES>>>(out);
    ddpll_unwrap_scan<<<1, NMODES>>>();
    ddpll_apply_kernel<<<NCHUNK, NMODES>>>(Er, Eim, out);
}

// round 17
// speedup vs baseline: 13.1259x; 1.6566x over previous
#include <cuda_runtime.h>
#include <math.h>

// DDPLL — fully chunk-parallel speculate/stitch/fix (R14-R16 validated). R17:
// 4-deep prefetch rings on every chain kernel (R16 regressed to 1-deep and paid
// ~100-200 cyc/step of exposed DRAM latency) + requantized chunking that fills
// all 148 SMs x 4 SMSPs = 592 warp-slots exactly.
//
//  K1 spec : 592 warp-items: 400 pilot chunks-items (NPS=50, warm 1200, body 400)
//            + 192 DD chunk-items (NC=24, warm 240, body 816, 2 fix seeds each)
//  K2 stitchP : chained 2*pi branch ints (pilot map periodicity)
//  K3 fixP    : warm 512 + body 400; last chunk appends exact 416-step DD stub
//  K4 stitchDD: chained pi/2 branch ints (QAM slicer symmetry), anchor = stub end
//  K5 fixDD   : two half-chunks per DD chunk: warm 128 + body 408
//  K6-K8      : unwrap partials / scan / apply+rotate (proven)
//
// FROZEN: per-step fp sequences (libdevice sincosf; XLA autodiff chain in pilot;
// QAM slicer in DD) — gate-safe R5/R7/R11/R13-R16. Warm margins kept at the
// R15/R16-proven values (pilot 1200+512, DD fix 128); DD spec warm 240 gives
// mean contraction e^-53 (0.22/step) before the fix warm even starts.

#define NSYMB   40000
#define NMODES  256
#define LEAD    20000

#define NPS     50
#define WPS     400            // NPS*WPS == LEAD
#define HP      1200
#define HFIXP   512

#define CH0     416            // exact DD stub; NC*W2 + CH0 == LEAD
#define NC      24
#define W2      816
#define WFD     408
#define HSPEC   240
#define HFIX    128

#define NCHUNK  2000
#define CHS     20

__device__ float g_suP[NMODES * NPS];
__device__ float g_swP[NMODES * NPS];
__device__ float g_svP[NMODES * NPS];
__device__ float g_noffP[NMODES * NPS];
__device__ float g_suD[NMODES * NC * 2];
__device__ float g_swD[NMODES * NC];
__device__ float g_svD[NMODES * NC];
__device__ float g_noffD[NMODES * NC];
__device__ float g_partials[NMODES * NCHUNK];
__device__ float g_boundary[NMODES * NCHUNK];

// ---- frozen pilot step (XLA autodiff chain) ----
__device__ __forceinline__ float pilot_step(float phi, float yr, float yi,
                                            float xr, float xi, float Kv)
{
    float s, c;
    sincosf(phi, &s, &c);
    const float zr = yr * c - yi * s;
    const float zi = yr * s + yi * c;
    const float dr = zr - xr;
    const float di = zi - xi;
    const float aa = fabsf(dr), ab = fabsf(di);
    const float mx = fmaxf(aa, ab);
    const float mn = fminf(aa, ab);
    const bool  z0 = (mx == 0.0f);
    const float den1 = z0 ? 1.0f : mx;
    const float r  = mn / den1;
    const float a  = mx * sqrtf(1.0f + r * r);
    const float den2 = z0 ? 1.0f : a;
    const float t  = a + a;
    const float qr = dr / den2;
    const float qi = (-di) / den2;
    const float dbr = t * qr;
    const float dbi = t * qi;
    const float ebr = dbr * yr - dbi * yi;
    const float ebi = dbr * yi + dbi * yr;
    const float g = -(ebr * s + ebi * c);
    return phi - Kv * g;
}

// ---- frozen DD step ----
__device__ __forceinline__ float dd_step(float phi, float yr, float yi, float Kv)
{
    const float QB = 0.6324555320336759f;
    const float L1 = 0.31622776601683794f;
    const float L3 = 0.9486832980505138f;
    float s, c;
    sincosf(phi, &s, &c);
    const float zr = yr * c - yi * s;
    const float zi = yr * s + yi * c;
    const float cr = copysignf((fabsf(zr) < QB) ? L1 : L3, zr);
    const float ci = copysignf((fabsf(zi) < QB) ? L1 : L3, zi);
    const float g = 2.0f * (zi * cr - zr * ci);
    return phi - Kv * g;
}

// K1: all speculative chains. 4 warp-items per 128-thread block (one per SMSP).
// All segment lengths are multiples of 4 -> clean 4-deep rings.
__global__ __launch_bounds__(128, 1)
void ddpll_spec_kernel(const float* __restrict__ Er,
                       const float* __restrict__ Eim,
                       const float* __restrict__ Txr,
                       const float* __restrict__ Txi,
                       const float* __restrict__ eta)
{
    const int item = blockIdx.x * 4 + (threadIdx.x >> 5);
    const int lane = threadIdx.x & 31;
    const float Kv = tanhf(eta[0]);

    if (item < NPS * 8) {
        // ---- pilot spec chunk ----
        const int c = item >> 3;
        const int m = (item & 7) * 32 + lane;
        const int k_sb  = c * WPS;
        const int k_end = k_sb + WPS;
        int kw = k_sb - HP;
        if (kw < 0) kw = 0;                 // clamped => exact orbit from phi(0)=0

        float phi = 0.0f;
        float u = 0.0f, w = 0.0f, v = 0.0f;

        float ry[4], rj[4], rx[4], rv[4];
#pragma unroll
        for (int j = 0; j < 4; ++j) {
            const int idx = (kw + j) * NMODES + m;
            ry[j] = Er[idx];  rj[j] = Eim[idx];
            rx[j] = Txr[idx]; rv[j] = Txi[idx];
        }
        for (int k0 = kw; k0 < k_end; k0 += 4) {
#pragma unroll
            for (int j = 0; j < 4; ++j) {
                const int k = k0 + j;
                const float yr = ry[j], yi = rj[j];
                const float xr = rx[j], xi = rv[j];
                if (k + 4 < k_end) {
                    const int idx = (k + 4) * NMODES + m;
                    ry[j] = Er[idx];  rj[j] = Eim[idx];
                    rx[j] = Txr[idx]; rv[j] = Txi[idx];
                }
                if (k == k_sb - HFIXP) u = phi;
                if (k == k_sb - 1)     w = phi;
                if (k == k_end - 1)    v = phi;
                phi = pilot_step(phi, yr, yi, xr, xi, Kv);
            }
        }
        g_suP[m * NPS + c] = u;
        g_swP[m * NPS + c] = w;
        g_svP[m * NPS + c] = v;
    } else {
        // ---- DD spec chunk ----
        const int t = item - NPS * 8;
        const int c = t >> 3;
        const int m = (t & 7) * 32 + lane;
        const int k_sb  = LEAD + CH0 + c * W2;
        const int k_end = k_sb + W2;
        const int kw    = k_sb - HSPEC;     // >= LEAD + CH0 - HSPEC >= LEAD

        float phi = 0.0f;
        float u0 = 0.0f, u1 = 0.0f, w = 0.0f, v = 0.0f;

        float ry[4], rj[4];
#pragma unroll
        for (int j = 0; j < 4; ++j) {
            const int idx = (kw + j) * NMODES + m;
            ry[j] = Er[idx]; rj[j] = Eim[idx];
        }
        for (int k0 = kw; k0 < k_end; k0 += 4) {
#pragma unroll
            for (int j = 0; j < 4; ++j) {
                const int k = k0 + j;
                const float yr = ry[j], yi = rj[j];
                if (k + 4 < k_end) {
                    const int idx = (k + 4) * NMODES + m;
                    ry[j] = Er[idx]; rj[j] = Eim[idx];
                }
                if (k == k_sb - HFIX)       u0 = phi;
                if (k == k_sb + WFD - HFIX) u1 = phi;
                if (k == k_sb - 1)          w  = phi;
                if (k == k_end - 1)         v  = phi;
                phi = dd_step(phi, yr, yi, Kv);
            }
        }
        g_suD[(m * NC + c) * 2 + 0] = u0;
        g_suD[(m * NC + c) * 2 + 1] = u1;
        g_swD[m * NC + c] = w;
        g_svD[m * NC + c] = v;
    }
}

// K2: pilot stitch — chained 2*pi branch ints.
__global__ __launch_bounds__(NMODES)
void ddpll_stitchP_kernel()
{
    const int m = threadIdx.x;
    const float INV2PI = 0.15915494309189535f;

    float anchor = g_svP[m * NPS + 0];     // chunk 0 is exact (clamped warm)
    float n = 0.0f;
    g_noffP[m * NPS + 0] = 0.0f;
    for (int c = 1; c < NPS; ++c) {
        const float wv = g_swP[m * NPS + c];
        n += rintf((wv - anchor) * INV2PI);
        g_noffP[m * NPS + c] = n;
        anchor = g_svP[m * NPS + c];
    }
}

// K3: pilot fix — de-rotate seed, warm HFIXP, write body. Last chunk appends stub.
__global__ __launch_bounds__(128, 1)
void ddpll_fixP_kernel(const float* __restrict__ Er,
                       const float* __restrict__ Eim,
                       const float* __restrict__ Txr,
                       const float* __restrict__ Txi,
                       const float* __restrict__ eta,
                       float*       __restrict__ out)
{
    const int item = blockIdx.x * 4 + (threadIdx.x >> 5);
    const int lane = threadIdx.x & 31;
    const int c = item >> 3;
    const int m = (item & 7) * 32 + lane;
    const float Kv = tanhf(eta[0]);
    float* __restrict__ phi_out = out + (size_t)NSYMB * NMODES * 2;

    const int k_sb  = c * WPS;
    const int k_end = k_sb + WPS;
    int kb = k_sb - HFIXP;

    float phi;
    if (kb <= 0) {                          // chunks 0,1: exact from the true IC
        kb = 0;
        phi = 0.0f;
    } else {
        const double n = (double)g_noffP[m * NPS + c];
        phi = (float)((double)g_suP[m * NPS + c] - n * 6.283185307179586);
    }

    float ry[4], rj[4], rx[4], rv[4];
#pragma unroll
    for (int j = 0; j < 4; ++j) {
        const int idx = (kb + j) * NMODES + m;
        ry[j] = Er[idx];  rj[j] = Eim[idx];
        rx[j] = Txr[idx]; rv[j] = Txi[idx];
    }
    for (int k0 = kb; k0 < k_end; k0 += 4) {
#pragma unroll
        for (int j = 0; j < 4; ++j) {
            const int k = k0 + j;
            const float yr = ry[j], yi = rj[j];
            const float xr = rx[j], xi = rv[j];
            if (k + 4 < k_end) {
                const int idx = (k + 4) * NMODES + m;
                ry[j] = Er[idx];  rj[j] = Eim[idx];
                rx[j] = Txr[idx]; rv[j] = Txi[idx];
            }
            if (k >= k_sb) __stcs(&phi_out[k * NMODES + m], phi);
            phi = pilot_step(phi, yr, yi, xr, xi, Kv);
        }
    }

    if (c == NPS - 1) {
        // exact DD stub [LEAD, LEAD+CH0)
        float sy[4], sj[4];
#pragma unroll
        for (int j = 0; j < 4; ++j) {
            const int idx = (LEAD + j) * NMODES + m;
            sy[j] = Er[idx]; sj[j] = Eim[idx];
        }
        for (int k0 = LEAD; k0 < LEAD + CH0; k0 += 4) {
#pragma unroll
            for (int j = 0; j < 4; ++j) {
                const int k = k0 + j;
                const float yr = sy[j], yi = sj[j];
                if (k + 4 < LEAD + CH0) {
                    const int idx = (k + 4) * NMODES + m;
                    sy[j] = Er[idx]; sj[j] = Eim[idx];
                }
                __stcs(&phi_out[k * NMODES + m], phi);
                phi = dd_step(phi, yr, yi, Kv);
            }
        }
    }
}

// K4: DD stitch — chained pi/2 branch ints; anchor = exact stub end.
__global__ __launch_bounds__(NMODES)
void ddpll_stitchDD_kernel(const float* __restrict__ out)
{
    const int m = threadIdx.x;
    const float* __restrict__ phi_in = out + (size_t)NSYMB * NMODES * 2;
    const float TOP = 0.63661977236758134f;   // 2/pi

    float anchor = phi_in[(LEAD + CH0 - 1) * NMODES + m];
    float n = 0.0f;
    for (int c = 0; c < NC; ++c) {
        const float wv = g_swD[m * NC + c];
        n += rintf((wv - anchor) * TOP);
        g_noffD[m * NC + c] = n;
        anchor = g_svD[m * NC + c];
    }
}

// K5: DD fix — two half-chunks per DD chunk (warm 128 + body 408).
__global__ __launch_bounds__(128, 1)
void ddpll_fixDD_kernel(const float* __restrict__ Er,
                        const float* __restrict__ Eim,
                        const float* __restrict__ eta,
                        float*       __restrict__ out)
{
    const int item = blockIdx.x * 4 + (threadIdx.x >> 5);   // 0 .. NC*2*8-1
    const int lane = threadIdx.x & 31;
    const int c = item >> 4;
    const int r = item & 15;
    const int h = r >> 3;
    const int m = (r & 7) * 32 + lane;
    const float Kv = tanhf(eta[0]);
    float* __restrict__ phi_out = out + (size_t)NSYMB * NMODES * 2;

    const int p     = LEAD + CH0 + c * W2 + h * WFD;
    const int k_beg = p - HFIX;
    const int k_end = p + WFD;               // (HFIX+WFD) % 4 == 0

    const double n = (double)g_noffD[m * NC + c];
    float phi = (float)((double)g_suD[(m * NC + c) * 2 + h] - n * 1.5707963267948966);

    float ry[4], rj[4];
#pragma unroll
    for (int j = 0; j < 4; ++j) {
        const int idx = (k_beg + j) * NMODES + m;
        ry[j] = Er[idx]; rj[j] = Eim[idx];
    }
    for (int k0 = k_beg; k0 < k_end; k0 += 4) {
#pragma unroll
        for (int j = 0; j < 4; ++j) {
            const int k = k0 + j;
            const float yr = ry[j], yi = rj[j];
            if (k + 4 < k_end) {
                const int idx = (k + 4) * NMODES + m;
                ry[j] = Er[idx]; rj[j] = Eim[idx];
            }
            if (k >= p) __stcs(&phi_out[k * NMODES + m], phi);
            phi = dd_step(phi, yr, yi, Kv);
        }
    }
}

// ---- unwrap (exact reference fp ops) ----
__device__ __forceinline__ float unwrap_corr(float prev, float cur)
{
    const float PERIOD   = 1.5707963705062866f;
    const float INTERVAL = 0.5f * PERIOD;
    const float dd = cur - prev;
    if (fabsf(dd) < INTERVAL) return 0.0f;
    float r2 = fmodf(dd + INTERVAL, PERIOD);
    if (r2 < 0.0f) r2 += PERIOD;
    float ddmod = r2 - INTERVAL;
    if (ddmod == -INTERVAL && dd > 0.0f) ddmod = INTERVAL;
    return ddmod - dd;
}

__global__ __launch_bounds__(NMODES)
void ddpll_unwrap_partials(const float* __restrict__ out)
{
    const int c = blockIdx.x;
    const int m = threadIdx.x;
    const float* __restrict__ phi_in = out + (size_t)NSYMB * NMODES * 2;

    float prev = (c == 0) ? 0.0f : phi_in[(c * CHS - 1) * NMODES + m];
    g_boundary[m * NCHUNK + c] = prev;

    float sum = 0.0f;
    for (int i = 0; i < CHS; ++i) {
        const int k = c * CHS + i;
        const float cur = phi_in[k * NMODES + m];
        if (k > 0) sum += unwrap_corr(prev, cur);
        prev = cur;
    }
    g_partials[m * NCHUNK + c] = sum;
}

__global__ __launch_bounds__(NMODES)
void ddpll_unwrap_scan()
{
    const int m = threadIdx.x;
    float run = 0.0f;
    for (int c = 0; c < NCHUNK; ++c) {
        const float v = g_partials[m * NCHUNK + c];
        g_partials[m * NCHUNK + c] = run;
        run += v;
    }
}

__global__ __launch_bounds__(NMODES)
void ddpll_apply_kernel(const float* __restrict__ Er,
                        const float* __restrict__ Eim,
                        float*       __restrict__ out)
{
    const int c = blockIdx.x;
    const int m = threadIdx.x;
    float* __restrict__ theta_io = out + (size_t)NSYMB * NMODES * 2;
    float2* __restrict__ eo_out  = reinterpret_cast<float2*>(out);

    float C    = g_partials[m * NCHUNK + c];
    float prev = g_boundary[m * NCHUNK + c];

    for (int i = 0; i < CHS; ++i) {
        const int k = c * CHS + i;
        const float cur = theta_io[k * NMODES + m];
        if (k > 0) C += unwrap_corr(prev, cur);
        prev = cur;

        const float th = cur + C;
        __stcs(&theta_io[k * NMODES + m], th);

        const float yr = Er[k * NMODES + m];
        const float yi = Eim[k * NMODES + m];
        float s, cc;
        __sincosf(th, &s, &cc);
        float2 eo;
        eo.x = yr * cc - yi * s;
        eo.y = yr * s + yi * cc;
        __stcs(&eo_out[k * NMODES + m], eo);
    }
}

extern "C" void kernel_launch(void* const* d_in, const int* in_sizes, int n_in,
                              void* d_out, int out_size)
{
    const float* Er  = (const float*)d_in[0];
    const float* Eim = (const float*)d_in[1];
    const float* Txr = (const float*)d_in[2];
    const float* Txi = (const float*)d_in[3];
    const float* eta = (const float*)d_in[4];
    float* out = (float*)d_out;

    ddpll_spec_kernel<<<(NPS * 8 + NC * 8) / 4, 128>>>(Er, Eim, Txr, Txi, eta);
    ddpll_stitchP_kernel<<<1, NMODES>>>();
    ddpll_fixP_kernel<<<NPS * 8 / 4, 128>>>(Er, Eim, Txr, Txi, eta, out);
    ddpll_stitchDD_kernel<<<1, NMODES>>>(out);
    ddpll_fixDD_kernel<<<NC * 2 * 8 / 4, 128>>>(Er, Eim, eta, out);
    ddpll_unwrap_partials<<<NCHUNK, NMODES>>>(out);
    ddpll_unwrap_scan<<<1, NMODES>>>();
    ddpll_apply_kernel<<<NCHUNK, NMODES>>>(Er, Eim, out);
}